// round 5
// baseline (speedup 1.0000x reference)
#include <cuda_runtime.h>
#include <cuda_bf16.h>
#include <stdint.h>
#include <string.h>

// Problem constants
#define B_ 4
#define S_ 2048
#define D_ 1024
#define H_ 16
#define HS_ 64
#define MTOT (B_ * S_)   // 8192

// ---------------------------------------------------------------------------
// Pre-split bf16 hi/lo scratch (static device arrays — no allocation allowed)
// ---------------------------------------------------------------------------
__device__ __nv_bfloat16 g_xh[(size_t)MTOT * D_], g_xl[(size_t)MTOT * D_];
__device__ __nv_bfloat16 g_wqh[(size_t)D_ * D_], g_wql[(size_t)D_ * D_];
__device__ __nv_bfloat16 g_wkh[(size_t)D_ * D_], g_wkl[(size_t)D_ * D_];
__device__ __nv_bfloat16 g_wvh[(size_t)D_ * D_], g_wvl[(size_t)D_ * D_];
__device__ __nv_bfloat16 g_woh[(size_t)D_ * D_], g_wol[(size_t)D_ * D_];
// q,k: [bh][s][hs] (q pre-scaled by 0.125); vt: [bh][hs][s]
__device__ __nv_bfloat16 g_qh[(size_t)64 * S_ * HS_], g_ql[(size_t)64 * S_ * HS_];
__device__ __nv_bfloat16 g_kh[(size_t)64 * S_ * HS_], g_kl[(size_t)64 * S_ * HS_];
__device__ __nv_bfloat16 g_vth[(size_t)64 * HS_ * S_], g_vtl[(size_t)64 * HS_ * S_];
__device__ __nv_bfloat16 g_ctxh[(size_t)MTOT * D_], g_ctxl[(size_t)MTOT * D_];

// ---------------------------------------------------------------------------
// PTX helpers (arch-portable: sm_80+, valid on compute_103)
// ---------------------------------------------------------------------------
__device__ __forceinline__ uint32_t smem_u32(const void* p) {
    uint32_t a;
    asm("{ .reg .u64 t; cvta.to.shared.u64 t, %1; cvt.u32.u64 %0, t; }"
        : "=r"(a) : "l"(p));
    return a;
}

#define CP_ASYNC16(dst, src) \
    asm volatile("cp.async.cg.shared.global [%0], [%1], 16;" \
        :: "r"(dst), "l"(src))
#define CP_COMMIT() asm volatile("cp.async.commit_group;" ::: "memory")
#define CP_WAIT(n)  asm volatile("cp.async.wait_group %0;" :: "n"(n) : "memory")

#define LDSM_X4(R, ADDR) \
    asm volatile("ldmatrix.sync.aligned.m8n8.x4.shared.b16 {%0,%1,%2,%3}, [%4];" \
        : "=r"((R)[0]), "=r"((R)[1]), "=r"((R)[2]), "=r"((R)[3]) : "r"(ADDR))

#define MMA16816(C, A, B0, B1) \
    asm volatile("mma.sync.aligned.m16n8k16.row.col.f32.bf16.bf16.f32 " \
        "{%0,%1,%2,%3}, {%4,%5,%6,%7}, {%8,%9}, {%0,%1,%2,%3};" \
        : "+f"((C)[0]), "+f"((C)[1]), "+f"((C)[2]), "+f"((C)[3]) \
        : "r"((A)[0]), "r"((A)[1]), "r"((A)[2]), "r"((A)[3]), \
          "r"((B0)), "r"((B1)))

// Pack two floats into bf16x2 (hi) and residual bf16x2 (lo)
__device__ __forceinline__ void pack_hl(float a, float b,
                                        uint32_t& hi, uint32_t& lo) {
    __nv_bfloat162 h = __float22bfloat162_rn(make_float2(a, b));
    float2 f = __bfloat1622float2(h);
    __nv_bfloat162 l = __float22bfloat162_rn(make_float2(a - f.x, b - f.y));
    memcpy(&hi, &h, 4);
    memcpy(&lo, &l, 4);
}

// ---------------------------------------------------------------------------
// Split kernel: fp32 -> bf16 hi/lo (one float4 per thread)
// ---------------------------------------------------------------------------
__global__ __launch_bounds__(256, 4) void split_kernel(
    const float4* __restrict__ src, uint2* __restrict__ dh,
    uint2* __restrict__ dl, int n4)
{
    const int i = blockIdx.x * 256 + threadIdx.x;
    if (i >= n4) return;
    float4 v = src[i];
    __nv_bfloat162 h01 = __float22bfloat162_rn(make_float2(v.x, v.y));
    __nv_bfloat162 h23 = __float22bfloat162_rn(make_float2(v.z, v.w));
    float2 f01 = __bfloat1622float2(h01);
    float2 f23 = __bfloat1622float2(h23);
    __nv_bfloat162 l01 = __float22bfloat162_rn(make_float2(v.x - f01.x, v.y - f01.y));
    __nv_bfloat162 l23 = __float22bfloat162_rn(make_float2(v.z - f23.x, v.w - f23.y));
    uint2 hv, lv;
    memcpy(&hv.x, &h01, 4); memcpy(&hv.y, &h23, 4);
    memcpy(&lv.x, &l01, 4); memcpy(&lv.y, &l23, 4);
    dh[i] = hv;
    dl[i] = lv;
}

// ---------------------------------------------------------------------------
// Split-bf16 GEMM, pure bf16 mainloop with 4-stage cp.async pipeline.
// C = Ah*Bh + Ah*Bl + Al*Bh (fp32 accum). CTA 128x128, BK=32, 8 warps (2x4).
// Smem per stage: 4 tiles (Ah/Al/Bh/Bl) 128 rows x pitch 80B = 40960B.
// MODE 0: A = x hi/lo, B = concat(Wq,Wk,Wv) hi/lo; epilogue splits to
//         q/k (bf16 hi/lo, q scaled 0.125) and v transposed (bf16 hi/lo).
// MODE 1: A = ctx hi/lo, B = Wo hi/lo; epilogue fp32 out + bias.
// ---------------------------------------------------------------------------
#define GTILE 10240u           // 128 * 80
#define GSTAGE 40960u          // 4 tiles
#define GEMM_DYN_SMEM (4 * 40960)

template<int MODE>
__global__ __launch_bounds__(256, 1) void gemm_kernel(
    const float* __restrict__ bo, float* __restrict__ outp)
{
    extern __shared__ char smem[];
    const int tid  = threadIdx.x;
    const int lane = tid & 31;
    const int wid  = tid >> 5;
    const int wm   = (wid >> 2) * 64;
    const int wn   = (wid & 3) * 32;
    const int m0   = blockIdx.x * 128;
    const int n0   = blockIdx.y * 128;

    const __nv_bfloat16 *Ah, *Al, *Bh, *Bl;
    int nbase;
    if (MODE == 0) {
        Ah = g_xh; Al = g_xl;
        const int mat = n0 >> 10;
        Bh = (mat == 0) ? g_wqh : ((mat == 1) ? g_wkh : g_wvh);
        Bl = (mat == 0) ? g_wql : ((mat == 1) ? g_wkl : g_wvl);
        nbase = n0 & 1023;
    } else {
        Ah = g_ctxh; Al = g_ctxl; Bh = g_woh; Bl = g_wol;
        nbase = n0;
    }

    // loader precompute: 8 x 16B cp.async per thread per stage
    const char* src[8];
    uint32_t dstoff[8];
#pragma unroll
    for (int i = 0; i < 8; i++) {
        const int idx = i * 256 + tid;
        const int tile = idx >> 9, c = idx & 511, row = c >> 2, col = c & 3;
        const __nv_bfloat16* bp =
            (tile == 0) ? Ah + (size_t)(m0 + row) * 1024 :
            (tile == 1) ? Al + (size_t)(m0 + row) * 1024 :
            (tile == 2) ? Bh + (size_t)(nbase + row) * 1024 :
                          Bl + (size_t)(nbase + row) * 1024;
        src[i] = (const char*)(bp + col * 8);
        dstoff[i] = (uint32_t)tile * GTILE + (uint32_t)row * 80u + (uint32_t)col * 16u;
    }
    const uint32_t s0 = smem_u32(smem);

    // prologue: stages 0..2  (stage s covers k bytes offset 64*s)
#pragma unroll
    for (int s = 0; s < 3; s++) {
#pragma unroll
        for (int i = 0; i < 8; i++)
            CP_ASYNC16(s0 + (uint32_t)s * GSTAGE + dstoff[i], src[i] + s * 64);
        CP_COMMIT();
    }

    float c[4][4][4];
#pragma unroll
    for (int i = 0; i < 4; i++)
#pragma unroll
        for (int j = 0; j < 4; j++)
#pragma unroll
            for (int q = 0; q < 4; q++) c[i][j][q] = 0.0f;

    const uint32_t aoff = (uint32_t)((lane & 15) * 80 + (lane >> 4) * 16);
    const uint32_t boff = (uint32_t)(((lane & 7) + ((lane >> 4) & 1) * 8) * 80
                                     + ((lane >> 3) & 1) * 16);

    for (int s = 0; s < 32; s++) {
        CP_WAIT(2);
        __syncthreads();
        if (s + 3 < 32) {
            const uint32_t sb2 = s0 + (uint32_t)((s + 3) & 3) * GSTAGE;
#pragma unroll
            for (int i = 0; i < 8; i++)
                CP_ASYNC16(sb2 + dstoff[i], src[i] + (s + 3) * 64);
        }
        CP_COMMIT();

        const uint32_t sb  = s0 + (uint32_t)(s & 3) * GSTAGE;
        const uint32_t sAh = sb + (uint32_t)(wm * 80) + aoff;
        const uint32_t sAl = sAh + GTILE;
        const uint32_t sBh = sb + 2 * GTILE + (uint32_t)(wn * 80) + boff;
        const uint32_t sBl = sBh + GTILE;
#pragma unroll
        for (int kk = 0; kk < 2; kk++) {
            uint32_t ah[4][4], al[4][4], bh4[2][4], bl4[2][4];
#pragma unroll
            for (int mi = 0; mi < 4; mi++) {
                LDSM_X4(ah[mi], sAh + mi * 1280 + kk * 32);
                LDSM_X4(al[mi], sAl + mi * 1280 + kk * 32);
            }
#pragma unroll
            for (int p = 0; p < 2; p++) {
                LDSM_X4(bh4[p], sBh + p * 1280 + kk * 32);
                LDSM_X4(bl4[p], sBl + p * 1280 + kk * 32);
            }
#pragma unroll
            for (int mi = 0; mi < 4; mi++)
#pragma unroll
                for (int p = 0; p < 2; p++) {
                    MMA16816(c[mi][2 * p],     ah[mi], bh4[p][0], bh4[p][1]);
                    MMA16816(c[mi][2 * p + 1], ah[mi], bh4[p][2], bh4[p][3]);
                    MMA16816(c[mi][2 * p],     ah[mi], bl4[p][0], bl4[p][1]);
                    MMA16816(c[mi][2 * p + 1], ah[mi], bl4[p][2], bl4[p][3]);
                    MMA16816(c[mi][2 * p],     al[mi], bh4[p][0], bh4[p][1]);
                    MMA16816(c[mi][2 * p + 1], al[mi], bh4[p][2], bh4[p][3]);
                }
        }
    }

    // ---- epilogue ----
    const int mrow = lane >> 2;
    const int ncol = (lane & 3) * 2;
#pragma unroll
    for (int mi = 0; mi < 4; mi++)
#pragma unroll
        for (int nj = 0; nj < 4; nj++) {
            const int col = n0 + wn + nj * 8 + ncol;
#pragma unroll
            for (int half = 0; half < 2; half++) {
                const int m = m0 + wm + mi * 16 + mrow + half * 8;
                const float v0 = c[mi][nj][half * 2 + 0];
                const float v1 = c[mi][nj][half * 2 + 1];
                if (MODE == 0) {
                    const int mat = col >> 10;
                    const int loc = col & 1023;
                    const int h = loc >> 6, hs = loc & 63;
                    const int b = m >> 11, si = m & 2047;
                    if (mat == 2) {
                        // V transposed bf16 hi/lo: [bh][hs][s]
                        const size_t p0 = ((size_t)(b * 16 + h) * 64 + hs) * 2048 + si;
                        __nv_bfloat16 h0 = __float2bfloat16(v0);
                        __nv_bfloat16 l0 = __float2bfloat16(v0 - __bfloat162float(h0));
                        __nv_bfloat16 h1 = __float2bfloat16(v1);
                        __nv_bfloat16 l1 = __float2bfloat16(v1 - __bfloat162float(h1));
                        g_vth[p0] = h0;        g_vtl[p0] = l0;
                        g_vth[p0 + 2048] = h1; g_vtl[p0 + 2048] = l1;
                    } else {
                        const float sc = (mat == 0) ? 0.125f : 1.0f;
                        uint32_t hi, lo;
                        pack_hl(v0 * sc, v1 * sc, hi, lo);
                        const size_t p0 = (((size_t)(b * 16 + h)) * 2048 + si) * 64 + hs;
                        if (mat == 0) {
                            *(uint32_t*)&g_qh[p0] = hi;
                            *(uint32_t*)&g_ql[p0] = lo;
                        } else {
                            *(uint32_t*)&g_kh[p0] = hi;
                            *(uint32_t*)&g_kl[p0] = lo;
                        }
                    }
                } else {
                    *(float2*)&outp[(size_t)m * 1024 + col] =
                        make_float2(v0 + bo[col], v1 + bo[col + 1]);
                }
            }
        }
}

// ---------------------------------------------------------------------------
// Flash attention, pure bf16 mainloop, cp.async double-buffered K/V tiles.
// CTA: 128 q-rows x one (b,h); 8 warps x 16 rows; K-tiles of 64 keys.
// Smem: Qh/Ql (128x pitch144 = 18432 each) + 2 stages x (Kh|Kl|Vh|Vl, 9216 each).
// ---------------------------------------------------------------------------
#define FTILE 9216u
#define FSTAGE 36864u
#define FLASH_SMEM (2 * 18432 + 2 * 36864)   // 110592

__global__ __launch_bounds__(256, 1) void flash_mma_kernel()
{
    extern __shared__ char fsm[];
    const uint32_t s0 = smem_u32(fsm);
    const uint32_t oQh = 0, oQl = 18432, oKV = 36864;

    const int tid = threadIdx.x, lane = tid & 31, wid = tid >> 5;
    const int qt = blockIdx.x, bh = blockIdx.y;
    const int wm = wid * 16;

    // ---- issue Q (hi/lo) via cp.async, one group ----
#pragma unroll
    for (int i = 0; i < 8; i++) {
        const int idx = i * 256 + tid;
        const int tile = idx >> 10, cc = idx & 1023, row = cc >> 3, col = cc & 7;
        const __nv_bfloat16* qsrc = ((tile == 0) ? g_qh : g_ql)
            + (size_t)bh * 131072 + (size_t)(qt * 128 + row) * 64 + col * 8;
        CP_ASYNC16(s0 + (uint32_t)tile * 18432u + (uint32_t)row * 144u
                       + (uint32_t)col * 16u, qsrc);
    }
    CP_COMMIT();

    // ---- KV loader precompute (per-kt byte strides) ----
    const char* skv[8];
    uint32_t dkv[8];
    int kstride[8];
#pragma unroll
    for (int i = 0; i < 8; i++) {
        const int idx = i * 256 + tid;
        const int tile = idx >> 9, cc = idx & 511, row = cc >> 3, col = cc & 7;
        const __nv_bfloat16* bp;
        if (tile == 0)      { bp = g_kh  + (size_t)bh * 131072 + (size_t)row * 64 + col * 8;   kstride[i] = 8192; }
        else if (tile == 1) { bp = g_kl  + (size_t)bh * 131072 + (size_t)row * 64 + col * 8;   kstride[i] = 8192; }
        else if (tile == 2) { bp = g_vth + (size_t)bh * 131072 + (size_t)row * 2048 + col * 8; kstride[i] = 128; }
        else                { bp = g_vtl + (size_t)bh * 131072 + (size_t)row * 2048 + col * 8; kstride[i] = 128; }
        skv[i] = (const char*)bp;
        dkv[i] = oKV + (uint32_t)tile * FTILE + (uint32_t)row * 144u + (uint32_t)col * 16u;
    }
    // issue kt=0 into stage 0
#pragma unroll
    for (int i = 0; i < 8; i++) CP_ASYNC16(s0 + dkv[i], skv[i]);
    CP_COMMIT();

    float o[8][4];
#pragma unroll
    for (int i = 0; i < 8; i++)
#pragma unroll
        for (int j = 0; j < 4; j++) o[i][j] = 0.0f;
    float mrow[2] = {-1e30f, -1e30f}, lrow[2] = {0.0f, 0.0f};

    const uint32_t aoffQ = (uint32_t)(wm * 144 + (lane & 15) * 144 + (lane >> 4) * 16);
    const uint32_t boff  = (uint32_t)(((lane & 7) + ((lane >> 4) & 1) * 8) * 144
                                      + ((lane >> 3) & 1) * 16);

    const int nkt = 2 * qt + 2;
    for (int kt = 0; kt < nkt; kt++) {
        CP_WAIT(0);
        __syncthreads();
        if (kt + 1 < nkt) {
            const uint32_t st2 = (uint32_t)((kt + 1) & 1) * FSTAGE;
#pragma unroll
            for (int i = 0; i < 8; i++)
                CP_ASYNC16(s0 + st2 + dkv[i], skv[i] + (size_t)(kt + 1) * kstride[i]);
        }
        CP_COMMIT();

        const uint32_t ss  = (uint32_t)(kt & 1) * FSTAGE;
        const uint32_t sKh = s0 + ss + oKV;
        const uint32_t sKl = sKh + FTILE;
        const uint32_t sVh = sKh + 2 * FTILE;
        const uint32_t sVl = sKh + 3 * FTILE;

        // ---- S = Q @ K^T (3-term split) ----
        float sc[8][4];
#pragma unroll
        for (int i = 0; i < 8; i++)
#pragma unroll
            for (int j = 0; j < 4; j++) sc[i][j] = 0.0f;
#pragma unroll
        for (int kk = 0; kk < 4; kk++) {
            uint32_t ah[4], al[4];
            LDSM_X4(ah, s0 + oQh + aoffQ + kk * 32);
            LDSM_X4(al, s0 + oQl + aoffQ + kk * 32);
#pragma unroll
            for (int nt2 = 0; nt2 < 4; nt2++) {
                uint32_t bh4[4], bl4[4];
                LDSM_X4(bh4, sKh + nt2 * 2304 + boff + kk * 32);
                LDSM_X4(bl4, sKl + nt2 * 2304 + boff + kk * 32);
                MMA16816(sc[2 * nt2],     ah, bh4[0], bh4[1]);
                MMA16816(sc[2 * nt2 + 1], ah, bh4[2], bh4[3]);
                MMA16816(sc[2 * nt2],     ah, bl4[0], bl4[1]);
                MMA16816(sc[2 * nt2 + 1], ah, bl4[2], bl4[3]);
                MMA16816(sc[2 * nt2],     al, bh4[0], bh4[1]);
                MMA16816(sc[2 * nt2 + 1], al, bh4[2], bh4[3]);
            }
        }

        // ---- causal mask ----
        if (kt >= 2 * qt) {
            const int baser = qt * 128 + wm + (lane >> 2);
            const int baseg = kt * 64 + ((lane & 3) << 1);
#pragma unroll
            for (int nt = 0; nt < 8; nt++)
#pragma unroll
                for (int j = 0; j < 4; j++) {
                    const int row = baser + ((j >> 1) << 3);
                    const int g   = baseg + nt * 8 + (j & 1);
                    if (g > row) sc[nt][j] = -1e30f;
                }
        }

        // ---- online softmax ----
#pragma unroll
        for (int hh = 0; hh < 2; hh++) {
            float rm = -1e30f;
#pragma unroll
            for (int nt = 0; nt < 8; nt++)
                rm = fmaxf(rm, fmaxf(sc[nt][2 * hh], sc[nt][2 * hh + 1]));
            rm = fmaxf(rm, __shfl_xor_sync(0xffffffffu, rm, 1));
            rm = fmaxf(rm, __shfl_xor_sync(0xffffffffu, rm, 2));
            const float mnew = fmaxf(mrow[hh], rm);
            const float corr = __expf(mrow[hh] - mnew);
            mrow[hh] = mnew;
            float rs = 0.0f;
#pragma unroll
            for (int nt = 0; nt < 8; nt++) {
                sc[nt][2 * hh]     = __expf(sc[nt][2 * hh] - mnew);
                sc[nt][2 * hh + 1] = __expf(sc[nt][2 * hh + 1] - mnew);
                rs += sc[nt][2 * hh] + sc[nt][2 * hh + 1];
            }
            rs += __shfl_xor_sync(0xffffffffu, rs, 1);
            rs += __shfl_xor_sync(0xffffffffu, rs, 2);
            lrow[hh] = lrow[hh] * corr + rs;
#pragma unroll
            for (int nt = 0; nt < 8; nt++) {
                o[nt][2 * hh]     *= corr;
                o[nt][2 * hh + 1] *= corr;
            }
        }

        // ---- O += P @ V (3-term split; P packed in regs) ----
#pragma unroll
        for (int t = 0; t < 4; t++) {
            uint32_t ap[4], alp[4];
            pack_hl(sc[2 * t][0],     sc[2 * t][1],     ap[0], alp[0]);
            pack_hl(sc[2 * t][2],     sc[2 * t][3],     ap[1], alp[1]);
            pack_hl(sc[2 * t + 1][0], sc[2 * t + 1][1], ap[2], alp[2]);
            pack_hl(sc[2 * t + 1][2], sc[2 * t + 1][3], ap[3], alp[3]);
#pragma unroll
            for (int nt2 = 0; nt2 < 4; nt2++) {
                uint32_t bh4[4], bl4[4];
                LDSM_X4(bh4, sVh + nt2 * 2304 + boff + t * 32);
                LDSM_X4(bl4, sVl + nt2 * 2304 + boff + t * 32);
                MMA16816(o[2 * nt2],     ap,  bh4[0], bh4[1]);
                MMA16816(o[2 * nt2 + 1], ap,  bh4[2], bh4[3]);
                MMA16816(o[2 * nt2],     ap,  bl4[0], bl4[1]);
                MMA16816(o[2 * nt2 + 1], ap,  bl4[2], bl4[3]);
                MMA16816(o[2 * nt2],     alp, bh4[0], bh4[1]);
                MMA16816(o[2 * nt2 + 1], alp, bh4[2], bh4[3]);
            }
        }
    }

    // ---- epilogue: normalize, split to ctx hi/lo bf16 ----
    const float inv0 = 1.0f / lrow[0];
    const float inv1 = 1.0f / lrow[1];
    const int b = bh >> 4, h = bh & 15;
    const int r0 = qt * 128 + wm + (lane >> 2);
    const int c0 = h * 64 + ((lane & 3) << 1);
#pragma unroll
    for (int nt = 0; nt < 8; nt++) {
        uint32_t hi, lo;
        pack_hl(o[nt][0] * inv0, o[nt][1] * inv0, hi, lo);
        const size_t p0 = (size_t)(b * 2048 + r0) * 1024 + c0 + nt * 8;
        *(uint32_t*)&g_ctxh[p0] = hi;
        *(uint32_t*)&g_ctxl[p0] = lo;
        pack_hl(o[nt][2] * inv1, o[nt][3] * inv1, hi, lo);
        const size_t p1 = (size_t)(b * 2048 + r0 + 8) * 1024 + c0 + nt * 8;
        *(uint32_t*)&g_ctxh[p1] = hi;
        *(uint32_t*)&g_ctxl[p1] = lo;
    }
}

// ---------------------------------------------------------------------------
// Launch.  Input order (metadata): x, Wk, Wq, Wv, Wo, bo
// ---------------------------------------------------------------------------
extern "C" void kernel_launch(void* const* d_in, const int* in_sizes, int n_in,
                              void* d_out, int out_size)
{
    const float* x  = (const float*)d_in[0];
    const float* Wk = (const float*)d_in[1];
    const float* Wq = (const float*)d_in[2];
    const float* Wv = (const float*)d_in[3];
    const float* Wo = (const float*)d_in[4];
    const float* bo = (const float*)d_in[5];
    float* out = (float*)d_out;

    static bool attr_done = false;
    if (!attr_done) {
        cudaFuncSetAttribute(gemm_kernel<0>,
                             cudaFuncAttributeMaxDynamicSharedMemorySize, GEMM_DYN_SMEM);
        cudaFuncSetAttribute(gemm_kernel<1>,
                             cudaFuncAttributeMaxDynamicSharedMemorySize, GEMM_DYN_SMEM);
        cudaFuncSetAttribute(flash_mma_kernel,
                             cudaFuncAttributeMaxDynamicSharedMemorySize, FLASH_SMEM);
        attr_done = true;
    }

    // Resolve device-global addresses (host-side, graph-capturable: no allocs)
    __nv_bfloat16 *xh, *xl, *wqh, *wql, *wkh, *wkl, *wvh, *wvl, *woh, *wol;
    cudaGetSymbolAddress((void**)&xh,  g_xh);  cudaGetSymbolAddress((void**)&xl,  g_xl);
    cudaGetSymbolAddress((void**)&wqh, g_wqh); cudaGetSymbolAddress((void**)&wql, g_wql);
    cudaGetSymbolAddress((void**)&wkh, g_wkh); cudaGetSymbolAddress((void**)&wkl, g_wkl);
    cudaGetSymbolAddress((void**)&wvh, g_wvh); cudaGetSymbolAddress((void**)&wvl, g_wvl);
    cudaGetSymbolAddress((void**)&woh, g_woh); cudaGetSymbolAddress((void**)&wol, g_wol);

    const int nx4 = MTOT * D_ / 4;     // 2M
    const int nw4 = D_ * D_ / 4;       // 256K
    split_kernel<<<nx4 / 256, 256>>>((const float4*)x,  (uint2*)xh,  (uint2*)xl,  nx4);
    split_kernel<<<nw4 / 256, 256>>>((const float4*)Wq, (uint2*)wqh, (uint2*)wql, nw4);
    split_kernel<<<nw4 / 256, 256>>>((const float4*)Wk, (uint2*)wkh, (uint2*)wkl, nw4);
    split_kernel<<<nw4 / 256, 256>>>((const float4*)Wv, (uint2*)wvh, (uint2*)wvl, nw4);
    split_kernel<<<nw4 / 256, 256>>>((const float4*)Wo, (uint2*)woh, (uint2*)wol, nw4);

    // QKV projection: M=8192, virtual N = [Wq | Wk | Wv] = 3072
    dim3 g1(MTOT / 128, 3072 / 128);     // 64 x 24
    gemm_kernel<0><<<g1, 256, GEMM_DYN_SMEM>>>(nullptr, nullptr);

    dim3 g2(S_ / 128, B_ * H_);          // 16 x 64
    flash_mma_kernel<<<g2, 256, FLASH_SMEM>>>();

    // Output projection: M=8192, N=1024 (+ bias)
    dim3 g3(MTOT / 128, 1024 / 128);     // 64 x 8
    gemm_kernel<1><<<g3, 256, GEMM_DYN_SMEM>>>(bo, out);
}

// round 6
// speedup vs baseline: 1.1711x; 1.1711x over previous
#include <cuda_runtime.h>
#include <cuda_bf16.h>
#include <stdint.h>
#include <string.h>

// Problem constants
#define B_ 4
#define S_ 2048
#define D_ 1024
#define H_ 16
#define HS_ 64
#define MTOT (B_ * S_)   // 8192

// ---------------------------------------------------------------------------
// Pre-split bf16 hi/lo scratch (static device arrays — no allocation allowed)
// ---------------------------------------------------------------------------
__device__ __nv_bfloat16 g_xh[(size_t)MTOT * D_], g_xl[(size_t)MTOT * D_];
__device__ __nv_bfloat16 g_wqh[(size_t)D_ * D_], g_wql[(size_t)D_ * D_];
__device__ __nv_bfloat16 g_wkh[(size_t)D_ * D_], g_wkl[(size_t)D_ * D_];
__device__ __nv_bfloat16 g_wvh[(size_t)D_ * D_], g_wvl[(size_t)D_ * D_];
__device__ __nv_bfloat16 g_woh[(size_t)D_ * D_], g_wol[(size_t)D_ * D_];
// q,k: [bh][s][hs] (q pre-scaled by 0.125); vt: [bh][hs][s]
__device__ __nv_bfloat16 g_qh[(size_t)64 * S_ * HS_], g_ql[(size_t)64 * S_ * HS_];
__device__ __nv_bfloat16 g_kh[(size_t)64 * S_ * HS_], g_kl[(size_t)64 * S_ * HS_];
__device__ __nv_bfloat16 g_vth[(size_t)64 * HS_ * S_], g_vtl[(size_t)64 * HS_ * S_];
__device__ __nv_bfloat16 g_ctxh[(size_t)MTOT * D_], g_ctxl[(size_t)MTOT * D_];

// ---------------------------------------------------------------------------
// PTX helpers (arch-portable: sm_80+, valid on compute_103)
// ---------------------------------------------------------------------------
__device__ __forceinline__ uint32_t smem_u32(const void* p) {
    uint32_t a;
    asm("{ .reg .u64 t; cvta.to.shared.u64 t, %1; cvt.u32.u64 %0, t; }"
        : "=r"(a) : "l"(p));
    return a;
}

#define CP_ASYNC16(dst, src) \
    asm volatile("cp.async.cg.shared.global [%0], [%1], 16;" \
        :: "r"(dst), "l"(src))
#define CP_COMMIT() asm volatile("cp.async.commit_group;" ::: "memory")
#define CP_WAIT(n)  asm volatile("cp.async.wait_group %0;" :: "n"(n) : "memory")

#define LDSM_X4(R, ADDR) \
    asm volatile("ldmatrix.sync.aligned.m8n8.x4.shared.b16 {%0,%1,%2,%3}, [%4];" \
        : "=r"((R)[0]), "=r"((R)[1]), "=r"((R)[2]), "=r"((R)[3]) : "r"(ADDR))

#define MMA16816(C, A, B0, B1) \
    asm volatile("mma.sync.aligned.m16n8k16.row.col.f32.bf16.bf16.f32 " \
        "{%0,%1,%2,%3}, {%4,%5,%6,%7}, {%8,%9}, {%0,%1,%2,%3};" \
        : "+f"((C)[0]), "+f"((C)[1]), "+f"((C)[2]), "+f"((C)[3]) \
        : "r"((A)[0]), "r"((A)[1]), "r"((A)[2]), "r"((A)[3]), \
          "r"((B0)), "r"((B1)))

// Pack two floats into bf16x2 (hi) and residual bf16x2 (lo)
__device__ __forceinline__ void pack_hl(float a, float b,
                                        uint32_t& hi, uint32_t& lo) {
    __nv_bfloat162 h = __float22bfloat162_rn(make_float2(a, b));
    float2 f = __bfloat1622float2(h);
    __nv_bfloat162 l = __float22bfloat162_rn(make_float2(a - f.x, b - f.y));
    memcpy(&hi, &h, 4);
    memcpy(&lo, &l, 4);
}

// ---------------------------------------------------------------------------
// Split kernel: fp32 -> bf16 hi/lo (one float4 per thread)
// ---------------------------------------------------------------------------
__global__ __launch_bounds__(256, 4) void split_kernel(
    const float4* __restrict__ src, uint2* __restrict__ dh,
    uint2* __restrict__ dl, int n4)
{
    const int i = blockIdx.x * 256 + threadIdx.x;
    if (i >= n4) return;
    float4 v = src[i];
    __nv_bfloat162 h01 = __float22bfloat162_rn(make_float2(v.x, v.y));
    __nv_bfloat162 h23 = __float22bfloat162_rn(make_float2(v.z, v.w));
    float2 f01 = __bfloat1622float2(h01);
    float2 f23 = __bfloat1622float2(h23);
    __nv_bfloat162 l01 = __float22bfloat162_rn(make_float2(v.x - f01.x, v.y - f01.y));
    __nv_bfloat162 l23 = __float22bfloat162_rn(make_float2(v.z - f23.x, v.w - f23.y));
    uint2 hv, lv;
    memcpy(&hv.x, &h01, 4); memcpy(&hv.y, &h23, 4);
    memcpy(&lv.x, &l01, 4); memcpy(&lv.y, &l23, 4);
    dh[i] = hv;
    dl[i] = lv;
}

// ---------------------------------------------------------------------------
// Split-bf16 GEMM, swizzled smem (no padding), 3-stage cp.async, 2 CTAs/SM.
// C = Ah*Bh + Ah*Bl + Al*Bh (fp32 accum). CTA 128x128, BK=32, 8 warps (2x4).
// Smem per stage: A-tile 128 rows x [hi 64B | lo 64B] = 16KB, B same = 32KB.
// Swizzle: 16B col index c (0..7) stored at c ^ (row & 7). Conflict-free.
// ---------------------------------------------------------------------------
#define GTILE 16384u
#define GSTAGE 32768u
#define GEMM_DYN_SMEM (3 * 32768)

template<int MODE>
__global__ __launch_bounds__(256, 2) void gemm_kernel(
    const float* __restrict__ bo, float* __restrict__ outp)
{
    extern __shared__ char smem[];
    const int tid  = threadIdx.x;
    const int lane = tid & 31;
    const int wid  = tid >> 5;
    const int wm   = (wid >> 2) * 64;
    const int wn   = (wid & 3) * 32;
    const int m0   = blockIdx.x * 128;
    const int n0   = blockIdx.y * 128;

    const __nv_bfloat16 *Ah, *Al, *Bh, *Bl;
    int nbase;
    if (MODE == 0) {
        Ah = g_xh; Al = g_xl;
        const int mat = n0 >> 10;
        Bh = (mat == 0) ? g_wqh : ((mat == 1) ? g_wkh : g_wvh);
        Bl = (mat == 0) ? g_wql : ((mat == 1) ? g_wkl : g_wvl);
        nbase = n0 & 1023;
    } else {
        Ah = g_ctxh; Al = g_ctxl; Bh = g_woh; Bl = g_wol;
        nbase = n0;
    }

    // Loader: 2048 16B chunks/stage, 8 per thread. tile = i>>2 (compile-time),
    // cc = (i&3)*256 + tid, row = cc>>3, col = cc&7 (col<4 = hi, col>=4 = lo).
    const char* src[8];
    uint32_t dstoff[8];
#pragma unroll
    for (int i = 0; i < 8; i++) {
        const int tile = i >> 2;                 // 0 = A, 1 = B
        const int cc   = (i & 3) * 256 + tid;
        const int row  = cc >> 3, col = cc & 7;
        const __nv_bfloat16* bp = (tile == 0)
            ? ((col < 4) ? Ah : Al) + (size_t)(m0 + row) * 1024
            : ((col < 4) ? Bh : Bl) + (size_t)(nbase + row) * 1024;
        src[i] = (const char*)(bp + (col & 3) * 8);
        dstoff[i] = (uint32_t)tile * GTILE + (uint32_t)row * 128u
                  + (uint32_t)((col ^ (row & 7)) << 4);
    }
    const uint32_t s0 = smem_u32(smem);

    // prologue: stages 0, 1
#pragma unroll
    for (int s = 0; s < 2; s++) {
#pragma unroll
        for (int i = 0; i < 8; i++)
            CP_ASYNC16(s0 + (uint32_t)s * GSTAGE + dstoff[i], src[i] + s * 64);
        CP_COMMIT();
    }

    float c[4][4][4];
#pragma unroll
    for (int i = 0; i < 4; i++)
#pragma unroll
        for (int j = 0; j < 4; j++)
#pragma unroll
            for (int q = 0; q < 4; q++) c[i][j][q] = 0.0f;

    const int l7 = lane & 7;
    const uint32_t arowoff = (uint32_t)((wm + (lane & 15)) * 128);
    const uint32_t browoff = (uint32_t)((wn + (lane & 7) + ((lane >> 4) & 1) * 8) * 128);

    int sb_idx = 0;   // stage buffer index (s % 3)
    for (int s = 0; s < 32; s++) {
        if (s == 31) { CP_WAIT(0); } else { CP_WAIT(1); }
        __syncthreads();
        if (s + 2 < 32) {
            const int nb = (sb_idx + 2 >= 3) ? sb_idx - 1 : sb_idx + 2;
            const uint32_t sb2 = s0 + (uint32_t)nb * GSTAGE;
#pragma unroll
            for (int i = 0; i < 8; i++)
                CP_ASYNC16(sb2 + dstoff[i], src[i] + (s + 2) * 64);
            CP_COMMIT();
        }

        const uint32_t sb = s0 + (uint32_t)sb_idx * GSTAGE;
        const uint32_t sA = sb + arowoff;
        const uint32_t sB = sb + GTILE + browoff;
#pragma unroll
        for (int kk = 0; kk < 2; kk++) {
            const uint32_t offA = (uint32_t)(((kk * 2 + (lane >> 4)) ^ l7) << 4);
            const uint32_t offB = (uint32_t)(((kk * 2 + ((lane >> 3) & 1)) ^ l7) << 4);
            uint32_t bh4[2][4], bl4[2][4];
#pragma unroll
            for (int p = 0; p < 2; p++) {
                LDSM_X4(bh4[p], sB + p * 2048 + offB);
                LDSM_X4(bl4[p], sB + p * 2048 + (offB ^ 64u));
            }
#pragma unroll
            for (int mi = 0; mi < 4; mi++) {
                uint32_t ah[4], al[4];
                LDSM_X4(ah, sA + mi * 2048 + offA);
                LDSM_X4(al, sA + mi * 2048 + (offA ^ 64u));
#pragma unroll
                for (int p = 0; p < 2; p++) {
                    MMA16816(c[mi][2 * p],     ah, bh4[p][0], bh4[p][1]);
                    MMA16816(c[mi][2 * p + 1], ah, bh4[p][2], bh4[p][3]);
                    MMA16816(c[mi][2 * p],     ah, bl4[p][0], bl4[p][1]);
                    MMA16816(c[mi][2 * p + 1], ah, bl4[p][2], bl4[p][3]);
                    MMA16816(c[mi][2 * p],     al, bh4[p][0], bh4[p][1]);
                    MMA16816(c[mi][2 * p + 1], al, bh4[p][2], bh4[p][3]);
                }
            }
        }
        sb_idx = (sb_idx + 1 >= 3) ? 0 : sb_idx + 1;
    }

    // ---- epilogue ----
    const int mrow = lane >> 2;
    const int ncol = (lane & 3) * 2;
#pragma unroll
    for (int mi = 0; mi < 4; mi++)
#pragma unroll
        for (int nj = 0; nj < 4; nj++) {
            const int col = n0 + wn + nj * 8 + ncol;
#pragma unroll
            for (int half = 0; half < 2; half++) {
                const int m = m0 + wm + mi * 16 + mrow + half * 8;
                const float v0 = c[mi][nj][half * 2 + 0];
                const float v1 = c[mi][nj][half * 2 + 1];
                if (MODE == 0) {
                    const int mat = col >> 10;
                    const int loc = col & 1023;
                    const int h = loc >> 6, hs = loc & 63;
                    const int b = m >> 11, si = m & 2047;
                    if (mat == 2) {
                        const size_t p0 = ((size_t)(b * 16 + h) * 64 + hs) * 2048 + si;
                        __nv_bfloat16 h0 = __float2bfloat16(v0);
                        __nv_bfloat16 l0 = __float2bfloat16(v0 - __bfloat162float(h0));
                        __nv_bfloat16 h1 = __float2bfloat16(v1);
                        __nv_bfloat16 l1 = __float2bfloat16(v1 - __bfloat162float(h1));
                        g_vth[p0] = h0;        g_vtl[p0] = l0;
                        g_vth[p0 + 2048] = h1; g_vtl[p0 + 2048] = l1;
                    } else {
                        const float sc = (mat == 0) ? 0.125f : 1.0f;
                        uint32_t hi, lo;
                        pack_hl(v0 * sc, v1 * sc, hi, lo);
                        const size_t p0 = (((size_t)(b * 16 + h)) * 2048 + si) * 64 + hs;
                        if (mat == 0) {
                            *(uint32_t*)&g_qh[p0] = hi;
                            *(uint32_t*)&g_ql[p0] = lo;
                        } else {
                            *(uint32_t*)&g_kh[p0] = hi;
                            *(uint32_t*)&g_kl[p0] = lo;
                        }
                    }
                } else {
                    *(float2*)&outp[(size_t)m * 1024 + col] =
                        make_float2(v0 + bo[col], v1 + bo[col + 1]);
                }
            }
        }
}

// ---------------------------------------------------------------------------
// Flash attention, swizzled smem (96KB -> 2 CTAs/SM), cp.async K/V dbl-buffer.
// CTA: 128 q-rows x one (b,h); 8 warps x 16 rows; K-tiles of 64 keys.
// Smem: Qh 16K | Ql 16K | 2 stages x (Kh 8K|Kl 8K|Vh 8K|Vl 8K).
// ---------------------------------------------------------------------------
#define FTILE 8192u
#define FSTAGE 32768u
#define FLASH_SMEM (32768 + 2 * 32768)   // 98304

__global__ __launch_bounds__(256, 2) void flash_mma_kernel()
{
    extern __shared__ char fsm[];
    const uint32_t s0 = smem_u32(fsm);
    const uint32_t oQl = 16384u, oKV = 32768u;

    const int tid = threadIdx.x, lane = tid & 31, wid = tid >> 5;
    const int qt = blockIdx.x, bh = blockIdx.y;
    const int wm = wid * 16;
    const int l7 = lane & 7;

    // ---- issue Q (hi/lo) via cp.async, one group ----
#pragma unroll
    for (int i = 0; i < 8; i++) {
        const int tile = i >> 2;                 // 0 = Qh, 1 = Ql
        const int cc   = (i & 3) * 256 + tid;
        const int row  = cc >> 3, col = cc & 7;
        const __nv_bfloat16* qsrc = ((tile == 0) ? g_qh : g_ql)
            + (size_t)bh * 131072 + (size_t)(qt * 128 + row) * 64 + col * 8;
        CP_ASYNC16(s0 + (uint32_t)tile * 16384u + (uint32_t)row * 128u
                       + (uint32_t)((col ^ (row & 7)) << 4), qsrc);
    }
    CP_COMMIT();

    // ---- KV loader precompute: tile = i>>1 (Kh,Kl,Vh,Vl), 64 rows x 8 cols ----
    const char* skv[8];
    uint32_t dkv[8];
#pragma unroll
    for (int i = 0; i < 8; i++) {
        const int tile = i >> 1;
        const int cc   = (i & 1) * 256 + tid;
        const int row  = cc >> 3, col = cc & 7;
        const __nv_bfloat16* bp;
        if (tile == 0)      bp = g_kh  + (size_t)bh * 131072 + (size_t)row * 64 + col * 8;
        else if (tile == 1) bp = g_kl  + (size_t)bh * 131072 + (size_t)row * 64 + col * 8;
        else if (tile == 2) bp = g_vth + (size_t)bh * 131072 + (size_t)row * 2048 + col * 8;
        else                bp = g_vtl + (size_t)bh * 131072 + (size_t)row * 2048 + col * 8;
        skv[i] = (const char*)bp;
        dkv[i] = oKV + (uint32_t)tile * FTILE + (uint32_t)row * 128u
               + (uint32_t)((col ^ (row & 7)) << 4);
    }
    // issue kt=0 into stage 0
#pragma unroll
    for (int i = 0; i < 8; i++) CP_ASYNC16(s0 + dkv[i], skv[i]);
    CP_COMMIT();

    float o[8][4];
#pragma unroll
    for (int i = 0; i < 8; i++)
#pragma unroll
        for (int j = 0; j < 4; j++) o[i][j] = 0.0f;
    float mrow[2] = {-1e30f, -1e30f}, lrow[2] = {0.0f, 0.0f};

    const uint32_t aQ = (uint32_t)((wm + (lane & 15)) * 128);
    const uint32_t bKV = (uint32_t)(((lane & 7) + ((lane >> 4) & 1) * 8) * 128);

    const int nkt = 2 * qt + 2;
    for (int kt = 0; kt < nkt; kt++) {
        CP_WAIT(0);
        __syncthreads();
        if (kt + 1 < nkt) {
            const uint32_t st2 = (uint32_t)((kt + 1) & 1) * FSTAGE;
            const int kof = kt + 1;
#pragma unroll
            for (int i = 0; i < 8; i++) {
                const int kstride = (i < 4) ? 8192 : 128;
                CP_ASYNC16(s0 + st2 + dkv[i], skv[i] + (size_t)kof * kstride);
            }
            CP_COMMIT();
        }

        const uint32_t ss  = (uint32_t)(kt & 1) * FSTAGE;
        const uint32_t sKh = s0 + ss + oKV + bKV;
        const uint32_t sVh = sKh + 2 * FTILE;

        // ---- S = Q @ K^T (3-term split) ----
        float sc[8][4];
#pragma unroll
        for (int i = 0; i < 8; i++)
#pragma unroll
            for (int j = 0; j < 4; j++) sc[i][j] = 0.0f;
#pragma unroll
        for (int kk = 0; kk < 4; kk++) {
            const uint32_t offA = (uint32_t)(((kk * 2 + (lane >> 4)) ^ l7) << 4);
            const uint32_t offB = (uint32_t)(((kk * 2 + ((lane >> 3) & 1)) ^ l7) << 4);
            uint32_t ah[4], al[4];
            LDSM_X4(ah, s0 + aQ + offA);
            LDSM_X4(al, s0 + oQl + aQ + offA);
#pragma unroll
            for (int nt2 = 0; nt2 < 4; nt2++) {
                uint32_t bh4[4], bl4[4];
                LDSM_X4(bh4, sKh + nt2 * 2048 + offB);
                LDSM_X4(bl4, sKh + FTILE + nt2 * 2048 + offB);
                MMA16816(sc[2 * nt2],     ah, bh4[0], bh4[1]);
                MMA16816(sc[2 * nt2 + 1], ah, bh4[2], bh4[3]);
                MMA16816(sc[2 * nt2],     ah, bl4[0], bl4[1]);
                MMA16816(sc[2 * nt2 + 1], ah, bl4[2], bl4[3]);
                MMA16816(sc[2 * nt2],     al, bh4[0], bh4[1]);
                MMA16816(sc[2 * nt2 + 1], al, bh4[2], bh4[3]);
            }
        }

        // ---- causal mask ----
        if (kt >= 2 * qt) {
            const int baser = qt * 128 + wm + (lane >> 2);
            const int baseg = kt * 64 + ((lane & 3) << 1);
#pragma unroll
            for (int nt = 0; nt < 8; nt++)
#pragma unroll
                for (int j = 0; j < 4; j++) {
                    const int row = baser + ((j >> 1) << 3);
                    const int g   = baseg + nt * 8 + (j & 1);
                    if (g > row) sc[nt][j] = -1e30f;
                }
        }

        // ---- online softmax ----
#pragma unroll
        for (int hh = 0; hh < 2; hh++) {
            float rm = -1e30f;
#pragma unroll
            for (int nt = 0; nt < 8; nt++)
                rm = fmaxf(rm, fmaxf(sc[nt][2 * hh], sc[nt][2 * hh + 1]));
            rm = fmaxf(rm, __shfl_xor_sync(0xffffffffu, rm, 1));
            rm = fmaxf(rm, __shfl_xor_sync(0xffffffffu, rm, 2));
            const float mnew = fmaxf(mrow[hh], rm);
            const float corr = __expf(mrow[hh] - mnew);
            mrow[hh] = mnew;
            float rs = 0.0f;
#pragma unroll
            for (int nt = 0; nt < 8; nt++) {
                sc[nt][2 * hh]     = __expf(sc[nt][2 * hh] - mnew);
                sc[nt][2 * hh + 1] = __expf(sc[nt][2 * hh + 1] - mnew);
                rs += sc[nt][2 * hh] + sc[nt][2 * hh + 1];
            }
            rs += __shfl_xor_sync(0xffffffffu, rs, 1);
            rs += __shfl_xor_sync(0xffffffffu, rs, 2);
            lrow[hh] = lrow[hh] * corr + rs;
#pragma unroll
            for (int nt = 0; nt < 8; nt++) {
                o[nt][2 * hh]     *= corr;
                o[nt][2 * hh + 1] *= corr;
            }
        }

        // ---- O += P @ V (3-term split; P packed in regs) ----
#pragma unroll
        for (int t = 0; t < 4; t++) {
            const uint32_t offB = (uint32_t)(((t * 2 + ((lane >> 3) & 1)) ^ l7) << 4);
            uint32_t ap[4], alp[4];
            pack_hl(sc[2 * t][0],     sc[2 * t][1],     ap[0], alp[0]);
            pack_hl(sc[2 * t][2],     sc[2 * t][3],     ap[1], alp[1]);
            pack_hl(sc[2 * t + 1][0], sc[2 * t + 1][1], ap[2], alp[2]);
            pack_hl(sc[2 * t + 1][2], sc[2 * t + 1][3], ap[3], alp[3]);
#pragma unroll
            for (int nt2 = 0; nt2 < 4; nt2++) {
                uint32_t bh4[4], bl4[4];
                LDSM_X4(bh4, sVh + nt2 * 2048 + offB);
                LDSM_X4(bl4, sVh + FTILE + nt2 * 2048 + offB);
                MMA16816(o[2 * nt2],     ap,  bh4[0], bh4[1]);
                MMA16816(o[2 * nt2 + 1], ap,  bh4[2], bh4[3]);
                MMA16816(o[2 * nt2],     ap,  bl4[0], bl4[1]);
                MMA16816(o[2 * nt2 + 1], ap,  bl4[2], bl4[3]);
                MMA16816(o[2 * nt2],     alp, bh4[0], bh4[1]);
                MMA16816(o[2 * nt2 + 1], alp, bh4[2], bh4[3]);
            }
        }
    }

    // ---- epilogue: normalize, split to ctx hi/lo bf16 ----
    const float inv0 = 1.0f / lrow[0];
    const float inv1 = 1.0f / lrow[1];
    const int b = bh >> 4, h = bh & 15;
    const int r0 = qt * 128 + wm + (lane >> 2);
    const int c0 = h * 64 + ((lane & 3) << 1);
#pragma unroll
    for (int nt = 0; nt < 8; nt++) {
        uint32_t hi, lo;
        pack_hl(o[nt][0] * inv0, o[nt][1] * inv0, hi, lo);
        const size_t p0 = (size_t)(b * 2048 + r0) * 1024 + c0 + nt * 8;
        *(uint32_t*)&g_ctxh[p0] = hi;
        *(uint32_t*)&g_ctxl[p0] = lo;
        pack_hl(o[nt][2] * inv1, o[nt][3] * inv1, hi, lo);
        const size_t p1 = (size_t)(b * 2048 + r0 + 8) * 1024 + c0 + nt * 8;
        *(uint32_t*)&g_ctxh[p1] = hi;
        *(uint32_t*)&g_ctxl[p1] = lo;
    }
}

// ---------------------------------------------------------------------------
// Launch.  Input order (metadata): x, Wk, Wq, Wv, Wo, bo
// ---------------------------------------------------------------------------
extern "C" void kernel_launch(void* const* d_in, const int* in_sizes, int n_in,
                              void* d_out, int out_size)
{
    const float* x  = (const float*)d_in[0];
    const float* Wk = (const float*)d_in[1];
    const float* Wq = (const float*)d_in[2];
    const float* Wv = (const float*)d_in[3];
    const float* Wo = (const float*)d_in[4];
    const float* bo = (const float*)d_in[5];
    float* out = (float*)d_out;

    static bool attr_done = false;
    if (!attr_done) {
        cudaFuncSetAttribute(gemm_kernel<0>,
                             cudaFuncAttributeMaxDynamicSharedMemorySize, GEMM_DYN_SMEM);
        cudaFuncSetAttribute(gemm_kernel<1>,
                             cudaFuncAttributeMaxDynamicSharedMemorySize, GEMM_DYN_SMEM);
        cudaFuncSetAttribute(flash_mma_kernel,
                             cudaFuncAttributeMaxDynamicSharedMemorySize, FLASH_SMEM);
        attr_done = true;
    }

    __nv_bfloat16 *xh, *xl, *wqh, *wql, *wkh, *wkl, *wvh, *wvl, *woh, *wol;
    cudaGetSymbolAddress((void**)&xh,  g_xh);  cudaGetSymbolAddress((void**)&xl,  g_xl);
    cudaGetSymbolAddress((void**)&wqh, g_wqh); cudaGetSymbolAddress((void**)&wql, g_wql);
    cudaGetSymbolAddress((void**)&wkh, g_wkh); cudaGetSymbolAddress((void**)&wkl, g_wkl);
    cudaGetSymbolAddress((void**)&wvh, g_wvh); cudaGetSymbolAddress((void**)&wvl, g_wvl);
    cudaGetSymbolAddress((void**)&woh, g_woh); cudaGetSymbolAddress((void**)&wol, g_wol);

    const int nx4 = MTOT * D_ / 4;     // 2M
    const int nw4 = D_ * D_ / 4;       // 256K
    split_kernel<<<nx4 / 256, 256>>>((const float4*)x,  (uint2*)xh,  (uint2*)xl,  nx4);
    split_kernel<<<nw4 / 256, 256>>>((const float4*)Wq, (uint2*)wqh, (uint2*)wql, nw4);
    split_kernel<<<nw4 / 256, 256>>>((const float4*)Wk, (uint2*)wkh, (uint2*)wkl, nw4);
    split_kernel<<<nw4 / 256, 256>>>((const float4*)Wv, (uint2*)wvh, (uint2*)wvl, nw4);
    split_kernel<<<nw4 / 256, 256>>>((const float4*)Wo, (uint2*)woh, (uint2*)wol, nw4);

    // QKV projection: M=8192, virtual N = [Wq | Wk | Wv] = 3072
    dim3 g1(MTOT / 128, 3072 / 128);     // 64 x 24
    gemm_kernel<0><<<g1, 256, GEMM_DYN_SMEM>>>(nullptr, nullptr);

    dim3 g2(S_ / 128, B_ * H_);          // 16 x 64
    flash_mma_kernel<<<g2, 256, FLASH_SMEM>>>();

    // Output projection: M=8192, N=1024 (+ bias)
    dim3 g3(MTOT / 128, 1024 / 128);     // 64 x 8
    gemm_kernel<1><<<g3, 256, GEMM_DYN_SMEM>>>(bo, out);
}

// round 7
// speedup vs baseline: 1.1919x; 1.0177x over previous
#include <cuda_runtime.h>
#include <cuda_bf16.h>
#include <stdint.h>
#include <string.h>

// Problem constants
#define B_ 4
#define S_ 2048
#define D_ 1024
#define H_ 16
#define HS_ 64
#define MTOT (B_ * S_)   // 8192

// ---------------------------------------------------------------------------
// Pre-split bf16 hi/lo scratch (static device arrays — no allocation allowed)
// ---------------------------------------------------------------------------
__device__ __nv_bfloat16 g_xh[(size_t)MTOT * D_], g_xl[(size_t)MTOT * D_];
__device__ __nv_bfloat16 g_wqh[(size_t)D_ * D_], g_wql[(size_t)D_ * D_];
__device__ __nv_bfloat16 g_wkh[(size_t)D_ * D_], g_wkl[(size_t)D_ * D_];
__device__ __nv_bfloat16 g_wvh[(size_t)D_ * D_], g_wvl[(size_t)D_ * D_];
__device__ __nv_bfloat16 g_woh[(size_t)D_ * D_], g_wol[(size_t)D_ * D_];
// q,k,v: all [bh][s][hs] (q pre-scaled by 0.125)
__device__ __nv_bfloat16 g_qh[(size_t)64 * S_ * HS_], g_ql[(size_t)64 * S_ * HS_];
__device__ __nv_bfloat16 g_kh[(size_t)64 * S_ * HS_], g_kl[(size_t)64 * S_ * HS_];
__device__ __nv_bfloat16 g_vh[(size_t)64 * S_ * HS_], g_vl[(size_t)64 * S_ * HS_];
__device__ __nv_bfloat16 g_ctxh[(size_t)MTOT * D_], g_ctxl[(size_t)MTOT * D_];

// ---------------------------------------------------------------------------
// PTX helpers (arch-portable: sm_80+, valid on compute_103)
// ---------------------------------------------------------------------------
__device__ __forceinline__ uint32_t smem_u32(const void* p) {
    uint32_t a;
    asm("{ .reg .u64 t; cvta.to.shared.u64 t, %1; cvt.u32.u64 %0, t; }"
        : "=r"(a) : "l"(p));
    return a;
}

#define CP_ASYNC16(dst, src) \
    asm volatile("cp.async.cg.shared.global [%0], [%1], 16;" \
        :: "r"(dst), "l"(src))
#define CP_COMMIT() asm volatile("cp.async.commit_group;" ::: "memory")
#define CP_WAIT(n)  asm volatile("cp.async.wait_group %0;" :: "n"(n) : "memory")

#define LDSM_X4(R, ADDR) \
    asm volatile("ldmatrix.sync.aligned.m8n8.x4.shared.b16 {%0,%1,%2,%3}, [%4];" \
        : "=r"((R)[0]), "=r"((R)[1]), "=r"((R)[2]), "=r"((R)[3]) : "r"(ADDR))

#define LDSM_X4_T(R, ADDR) \
    asm volatile("ldmatrix.sync.aligned.m8n8.x4.trans.shared.b16 {%0,%1,%2,%3}, [%4];" \
        : "=r"((R)[0]), "=r"((R)[1]), "=r"((R)[2]), "=r"((R)[3]) : "r"(ADDR))

#define MMA16816(C, A, B0, B1) \
    asm volatile("mma.sync.aligned.m16n8k16.row.col.f32.bf16.bf16.f32 " \
        "{%0,%1,%2,%3}, {%4,%5,%6,%7}, {%8,%9}, {%0,%1,%2,%3};" \
        : "+f"((C)[0]), "+f"((C)[1]), "+f"((C)[2]), "+f"((C)[3]) \
        : "r"((A)[0]), "r"((A)[1]), "r"((A)[2]), "r"((A)[3]), \
          "r"((B0)), "r"((B1)))

// Pack two floats into bf16x2 (hi) and residual bf16x2 (lo)
__device__ __forceinline__ void pack_hl(float a, float b,
                                        uint32_t& hi, uint32_t& lo) {
    __nv_bfloat162 h = __float22bfloat162_rn(make_float2(a, b));
    float2 f = __bfloat1622float2(h);
    __nv_bfloat162 l = __float22bfloat162_rn(make_float2(a - f.x, b - f.y));
    memcpy(&hi, &h, 4);
    memcpy(&lo, &l, 4);
}

// ---------------------------------------------------------------------------
// Combined split kernel: fp32 -> bf16 hi/lo for x + 4 weights, one launch.
// Grid: [0,8192) = x, then 1024 blocks each for Wq, Wk, Wv, Wo.
// ---------------------------------------------------------------------------
__global__ __launch_bounds__(256, 4) void split_all_kernel(
    const float4* __restrict__ x,  const float4* __restrict__ Wq,
    const float4* __restrict__ Wk, const float4* __restrict__ Wv,
    const float4* __restrict__ Wo)
{
    const int bid = blockIdx.x;
    const float4* src;
    uint2 *dh, *dl;
    int base;
    if (bid < 8192)      { src = x;  dh = (uint2*)g_xh;  dl = (uint2*)g_xl;  base = bid; }
    else if (bid < 9216) { src = Wq; dh = (uint2*)g_wqh; dl = (uint2*)g_wql; base = bid - 8192; }
    else if (bid < 10240){ src = Wk; dh = (uint2*)g_wkh; dl = (uint2*)g_wkl; base = bid - 9216; }
    else if (bid < 11264){ src = Wv; dh = (uint2*)g_wvh; dl = (uint2*)g_wvl; base = bid - 10240; }
    else                 { src = Wo; dh = (uint2*)g_woh; dl = (uint2*)g_wol; base = bid - 11264; }
    const int i = base * 256 + threadIdx.x;
    float4 v = src[i];
    __nv_bfloat162 h01 = __float22bfloat162_rn(make_float2(v.x, v.y));
    __nv_bfloat162 h23 = __float22bfloat162_rn(make_float2(v.z, v.w));
    float2 f01 = __bfloat1622float2(h01);
    float2 f23 = __bfloat1622float2(h23);
    __nv_bfloat162 l01 = __float22bfloat162_rn(make_float2(v.x - f01.x, v.y - f01.y));
    __nv_bfloat162 l23 = __float22bfloat162_rn(make_float2(v.z - f23.x, v.w - f23.y));
    uint2 hv, lv;
    memcpy(&hv.x, &h01, 4); memcpy(&hv.y, &h23, 4);
    memcpy(&lv.x, &l01, 4); memcpy(&lv.y, &l23, 4);
    dh[i] = hv;
    dl[i] = lv;
}

// ---------------------------------------------------------------------------
// Split-bf16 GEMM, swizzled smem, 3-stage cp.async, 2 CTAs/SM.
// C = Ah*Bh + Ah*Bl + Al*Bh (fp32 accum). CTA 128x128, BK=32, 8 warps (2x4).
// ---------------------------------------------------------------------------
#define GTILE 16384u
#define GSTAGE 32768u
#define GEMM_DYN_SMEM (3 * 32768)

template<int MODE>
__global__ __launch_bounds__(256, 2) void gemm_kernel(
    const float* __restrict__ bo, float* __restrict__ outp)
{
    extern __shared__ char smem[];
    const int tid  = threadIdx.x;
    const int lane = tid & 31;
    const int wid  = tid >> 5;
    const int wm   = (wid >> 2) * 64;
    const int wn   = (wid & 3) * 32;
    const int m0   = blockIdx.x * 128;
    const int n0   = blockIdx.y * 128;

    const __nv_bfloat16 *Ah, *Al, *Bh, *Bl;
    int nbase;
    if (MODE == 0) {
        Ah = g_xh; Al = g_xl;
        const int mat = n0 >> 10;
        Bh = (mat == 0) ? g_wqh : ((mat == 1) ? g_wkh : g_wvh);
        Bl = (mat == 0) ? g_wql : ((mat == 1) ? g_wkl : g_wvl);
        nbase = n0 & 1023;
    } else {
        Ah = g_ctxh; Al = g_ctxl; Bh = g_woh; Bl = g_wol;
        nbase = n0;
    }

    const char* src[8];
    uint32_t dstoff[8];
#pragma unroll
    for (int i = 0; i < 8; i++) {
        const int tile = i >> 2;                 // 0 = A, 1 = B
        const int cc   = (i & 3) * 256 + tid;
        const int row  = cc >> 3, col = cc & 7;
        const __nv_bfloat16* bp = (tile == 0)
            ? ((col < 4) ? Ah : Al) + (size_t)(m0 + row) * 1024
            : ((col < 4) ? Bh : Bl) + (size_t)(nbase + row) * 1024;
        src[i] = (const char*)(bp + (col & 3) * 8);
        dstoff[i] = (uint32_t)tile * GTILE + (uint32_t)row * 128u
                  + (uint32_t)((col ^ (row & 7)) << 4);
    }
    const uint32_t s0 = smem_u32(smem);

#pragma unroll
    for (int s = 0; s < 2; s++) {
#pragma unroll
        for (int i = 0; i < 8; i++)
            CP_ASYNC16(s0 + (uint32_t)s * GSTAGE + dstoff[i], src[i] + s * 64);
        CP_COMMIT();
    }

    float c[4][4][4];
#pragma unroll
    for (int i = 0; i < 4; i++)
#pragma unroll
        for (int j = 0; j < 4; j++)
#pragma unroll
            for (int q = 0; q < 4; q++) c[i][j][q] = 0.0f;

    const int l7 = lane & 7;
    const uint32_t arowoff = (uint32_t)((wm + (lane & 15)) * 128);
    const uint32_t browoff = (uint32_t)((wn + (lane & 7) + ((lane >> 4) & 1) * 8) * 128);

    int sb_idx = 0;
    for (int s = 0; s < 32; s++) {
        if (s == 31) { CP_WAIT(0); } else { CP_WAIT(1); }
        __syncthreads();
        if (s + 2 < 32) {
            const int nb = (sb_idx + 2 >= 3) ? sb_idx - 1 : sb_idx + 2;
            const uint32_t sb2 = s0 + (uint32_t)nb * GSTAGE;
#pragma unroll
            for (int i = 0; i < 8; i++)
                CP_ASYNC16(sb2 + dstoff[i], src[i] + (s + 2) * 64);
            CP_COMMIT();
        }

        const uint32_t sb = s0 + (uint32_t)sb_idx * GSTAGE;
        const uint32_t sA = sb + arowoff;
        const uint32_t sB = sb + GTILE + browoff;
#pragma unroll
        for (int kk = 0; kk < 2; kk++) {
            const uint32_t offA = (uint32_t)(((kk * 2 + (lane >> 4)) ^ l7) << 4);
            const uint32_t offB = (uint32_t)(((kk * 2 + ((lane >> 3) & 1)) ^ l7) << 4);
            uint32_t bh4[2][4], bl4[2][4];
#pragma unroll
            for (int p = 0; p < 2; p++) {
                LDSM_X4(bh4[p], sB + p * 2048 + offB);
                LDSM_X4(bl4[p], sB + p * 2048 + (offB ^ 64u));
            }
#pragma unroll
            for (int mi = 0; mi < 4; mi++) {
                uint32_t ah[4], al[4];
                LDSM_X4(ah, sA + mi * 2048 + offA);
                LDSM_X4(al, sA + mi * 2048 + (offA ^ 64u));
#pragma unroll
                for (int p = 0; p < 2; p++) {
                    MMA16816(c[mi][2 * p],     ah, bh4[p][0], bh4[p][1]);
                    MMA16816(c[mi][2 * p + 1], ah, bh4[p][2], bh4[p][3]);
                    MMA16816(c[mi][2 * p],     ah, bl4[p][0], bl4[p][1]);
                    MMA16816(c[mi][2 * p + 1], ah, bl4[p][2], bl4[p][3]);
                    MMA16816(c[mi][2 * p],     al, bh4[p][0], bh4[p][1]);
                    MMA16816(c[mi][2 * p + 1], al, bh4[p][2], bh4[p][3]);
                }
            }
        }
        sb_idx = (sb_idx + 1 >= 3) ? 0 : sb_idx + 1;
    }

    // ---- epilogue (all coalesced uint32/float2 stores now) ----
    const int mrow = lane >> 2;
    const int ncol = (lane & 3) * 2;
#pragma unroll
    for (int mi = 0; mi < 4; mi++)
#pragma unroll
        for (int nj = 0; nj < 4; nj++) {
            const int col = n0 + wn + nj * 8 + ncol;
#pragma unroll
            for (int half = 0; half < 2; half++) {
                const int m = m0 + wm + mi * 16 + mrow + half * 8;
                const float v0 = c[mi][nj][half * 2 + 0];
                const float v1 = c[mi][nj][half * 2 + 1];
                if (MODE == 0) {
                    const int mat = col >> 10;
                    const int loc = col & 1023;
                    const int h = loc >> 6, hs = loc & 63;
                    const int b = m >> 11, si = m & 2047;
                    const float sc = (mat == 0) ? 0.125f : 1.0f;
                    uint32_t hi, lo;
                    pack_hl(v0 * sc, v1 * sc, hi, lo);
                    __nv_bfloat16* dsth = (mat == 0) ? g_qh : ((mat == 1) ? g_kh : g_vh);
                    __nv_bfloat16* dstl = (mat == 0) ? g_ql : ((mat == 1) ? g_kl : g_vl);
                    const size_t p0 = (((size_t)(b * 16 + h)) * 2048 + si) * 64 + hs;
                    *(uint32_t*)&dsth[p0] = hi;
                    *(uint32_t*)&dstl[p0] = lo;
                } else {
                    *(float2*)&outp[(size_t)m * 1024 + col] =
                        make_float2(v0 + bo[col], v1 + bo[col + 1]);
                }
            }
        }
}

// ---------------------------------------------------------------------------
// Flash attention: swizzled smem (96KB, 2 CTAs/SM), cp.async K/V dbl-buffer,
// V loaded [key][hs] like K and consumed via ldmatrix.x4.trans for P@V.
// qt reversed (heaviest CTAs first) for wave balance.
// ---------------------------------------------------------------------------
#define FTILE 8192u
#define FSTAGE 32768u
#define FLASH_SMEM (32768 + 2 * 32768)   // 98304

__global__ __launch_bounds__(256, 2) void flash_mma_kernel()
{
    extern __shared__ char fsm[];
    const uint32_t s0 = smem_u32(fsm);
    const uint32_t oQl = 16384u, oKV = 32768u;

    const int tid = threadIdx.x, lane = tid & 31, wid = tid >> 5;
    const int qt = (int)gridDim.x - 1 - (int)blockIdx.x;   // heavy first
    const int bh = blockIdx.y;
    const int wm = wid * 16;
    const int l7 = lane & 7;

    // ---- issue Q (hi/lo) via cp.async, one group ----
#pragma unroll
    for (int i = 0; i < 8; i++) {
        const int tile = i >> 2;                 // 0 = Qh, 1 = Ql
        const int cc   = (i & 3) * 256 + tid;
        const int row  = cc >> 3, col = cc & 7;
        const __nv_bfloat16* qsrc = ((tile == 0) ? g_qh : g_ql)
            + (size_t)bh * 131072 + (size_t)(qt * 128 + row) * 64 + col * 8;
        CP_ASYNC16(s0 + (uint32_t)tile * 16384u + (uint32_t)row * 128u
                       + (uint32_t)((col ^ (row & 7)) << 4), qsrc);
    }
    CP_COMMIT();

    // ---- KV loader: 4 tiles (Kh,Kl,Vh,Vl), all [64 keys][64 hs], stride 8192 ----
    const char* skv[8];
    uint32_t dkv[8];
#pragma unroll
    for (int i = 0; i < 8; i++) {
        const int tile = i >> 1;
        const int cc   = (i & 1) * 256 + tid;
        const int row  = cc >> 3, col = cc & 7;
        const __nv_bfloat16* bp =
            ((tile == 0) ? g_kh : (tile == 1) ? g_kl : (tile == 2) ? g_vh : g_vl)
            + (size_t)bh * 131072 + (size_t)row * 64 + col * 8;
        skv[i] = (const char*)bp;
        dkv[i] = oKV + (uint32_t)tile * FTILE + (uint32_t)row * 128u
               + (uint32_t)((col ^ (row & 7)) << 4);
    }
#pragma unroll
    for (int i = 0; i < 8; i++) CP_ASYNC16(s0 + dkv[i], skv[i]);
    CP_COMMIT();

    float o[8][4];
#pragma unroll
    for (int i = 0; i < 8; i++)
#pragma unroll
        for (int j = 0; j < 4; j++) o[i][j] = 0.0f;
    float mrow[2] = {-1e30f, -1e30f}, lrow[2] = {0.0f, 0.0f};

    const uint32_t aQ  = (uint32_t)((wm + (lane & 15)) * 128);
    const uint32_t bKV = (uint32_t)(((lane & 7) + ((lane >> 4) & 1) * 8) * 128);
    // V trans-ldmatrix: per-lane key row within 16-chunk, hi/lo n-group select
    const int vrowb = (lane & 7) + 8 * ((lane >> 3) & 1);
    const int vsel  = (lane >> 4) & 1;

    const int nkt = 2 * qt + 2;
    for (int kt = 0; kt < nkt; kt++) {
        CP_WAIT(0);
        __syncthreads();
        if (kt + 1 < nkt) {
            const uint32_t st2 = (uint32_t)((kt + 1) & 1) * FSTAGE;
#pragma unroll
            for (int i = 0; i < 8; i++)
                CP_ASYNC16(s0 + st2 + dkv[i], skv[i] + (size_t)(kt + 1) * 8192);
            CP_COMMIT();
        }

        const uint32_t ss  = (uint32_t)(kt & 1) * FSTAGE;
        const uint32_t sKh = s0 + ss + oKV + bKV;
        const uint32_t sV  = s0 + ss + oKV + 2 * FTILE;   // Vh tile base

        // ---- S = Q @ K^T (3-term split) ----
        float sc[8][4];
#pragma unroll
        for (int i = 0; i < 8; i++)
#pragma unroll
            for (int j = 0; j < 4; j++) sc[i][j] = 0.0f;
#pragma unroll
        for (int kk = 0; kk < 4; kk++) {
            const uint32_t offA = (uint32_t)(((kk * 2 + (lane >> 4)) ^ l7) << 4);
            const uint32_t offB = (uint32_t)(((kk * 2 + ((lane >> 3) & 1)) ^ l7) << 4);
            uint32_t ah[4], al[4];
            LDSM_X4(ah, s0 + aQ + offA);
            LDSM_X4(al, s0 + oQl + aQ + offA);
#pragma unroll
            for (int nt2 = 0; nt2 < 4; nt2++) {
                uint32_t bh4[4], bl4[4];
                LDSM_X4(bh4, sKh + nt2 * 2048 + offB);
                LDSM_X4(bl4, sKh + FTILE + nt2 * 2048 + offB);
                MMA16816(sc[2 * nt2],     ah, bh4[0], bh4[1]);
                MMA16816(sc[2 * nt2 + 1], ah, bh4[2], bh4[3]);
                MMA16816(sc[2 * nt2],     ah, bl4[0], bl4[1]);
                MMA16816(sc[2 * nt2 + 1], ah, bl4[2], bl4[3]);
                MMA16816(sc[2 * nt2],     al, bh4[0], bh4[1]);
                MMA16816(sc[2 * nt2 + 1], al, bh4[2], bh4[3]);
            }
        }

        // ---- causal mask ----
        if (kt >= 2 * qt) {
            const int baser = qt * 128 + wm + (lane >> 2);
            const int baseg = kt * 64 + ((lane & 3) << 1);
#pragma unroll
            for (int nt = 0; nt < 8; nt++)
#pragma unroll
                for (int j = 0; j < 4; j++) {
                    const int row = baser + ((j >> 1) << 3);
                    const int g   = baseg + nt * 8 + (j & 1);
                    if (g > row) sc[nt][j] = -1e30f;
                }
        }

        // ---- online softmax ----
#pragma unroll
        for (int hh = 0; hh < 2; hh++) {
            float rm = -1e30f;
#pragma unroll
            for (int nt = 0; nt < 8; nt++)
                rm = fmaxf(rm, fmaxf(sc[nt][2 * hh], sc[nt][2 * hh + 1]));
            rm = fmaxf(rm, __shfl_xor_sync(0xffffffffu, rm, 1));
            rm = fmaxf(rm, __shfl_xor_sync(0xffffffffu, rm, 2));
            const float mnew = fmaxf(mrow[hh], rm);
            const float corr = __expf(mrow[hh] - mnew);
            mrow[hh] = mnew;
            float rs = 0.0f;
#pragma unroll
            for (int nt = 0; nt < 8; nt++) {
                sc[nt][2 * hh]     = __expf(sc[nt][2 * hh] - mnew);
                sc[nt][2 * hh + 1] = __expf(sc[nt][2 * hh + 1] - mnew);
                rs += sc[nt][2 * hh] + sc[nt][2 * hh + 1];
            }
            rs += __shfl_xor_sync(0xffffffffu, rs, 1);
            rs += __shfl_xor_sync(0xffffffffu, rs, 2);
            lrow[hh] = lrow[hh] * corr + rs;
#pragma unroll
            for (int nt = 0; nt < 8; nt++) {
                o[nt][2 * hh]     *= corr;
                o[nt][2 * hh + 1] *= corr;
            }
        }

        // ---- O += P @ V (3-term split; V via trans-ldmatrix from [key][hs]) ----
#pragma unroll
        for (int t = 0; t < 4; t++) {
            const int vrow = t * 16 + vrowb;
            uint32_t ap[4], alp[4];
            pack_hl(sc[2 * t][0],     sc[2 * t][1],     ap[0], alp[0]);
            pack_hl(sc[2 * t][2],     sc[2 * t][3],     ap[1], alp[1]);
            pack_hl(sc[2 * t + 1][0], sc[2 * t + 1][1], ap[2], alp[2]);
            pack_hl(sc[2 * t + 1][2], sc[2 * t + 1][3], ap[3], alp[3]);
#pragma unroll
            for (int nt2 = 0; nt2 < 4; nt2++) {
                const int col16 = nt2 * 2 + vsel;
                const uint32_t vaddr = (uint32_t)(vrow * 128)
                                     + (uint32_t)((col16 ^ (vrow & 7)) << 4);
                uint32_t bh4[4], bl4[4];
                LDSM_X4_T(bh4, sV + vaddr);
                LDSM_X4_T(bl4, sV + FTILE + vaddr);
                MMA16816(o[2 * nt2],     ap,  bh4[0], bh4[1]);
                MMA16816(o[2 * nt2 + 1], ap,  bh4[2], bh4[3]);
                MMA16816(o[2 * nt2],     ap,  bl4[0], bl4[1]);
                MMA16816(o[2 * nt2 + 1], ap,  bl4[2], bl4[3]);
                MMA16816(o[2 * nt2],     alp, bh4[0], bh4[1]);
                MMA16816(o[2 * nt2 + 1], alp, bh4[2], bh4[3]);
            }
        }
    }

    // ---- epilogue: normalize, split to ctx hi/lo bf16 ----
    const float inv0 = 1.0f / lrow[0];
    const float inv1 = 1.0f / lrow[1];
    const int b = bh >> 4, h = bh & 15;
    const int r0 = qt * 128 + wm + (lane >> 2);
    const int c0 = h * 64 + ((lane & 3) << 1);
#pragma unroll
    for (int nt = 0; nt < 8; nt++) {
        uint32_t hi, lo;
        pack_hl(o[nt][0] * inv0, o[nt][1] * inv0, hi, lo);
        const size_t p0 = (size_t)(b * 2048 + r0) * 1024 + c0 + nt * 8;
        *(uint32_t*)&g_ctxh[p0] = hi;
        *(uint32_t*)&g_ctxl[p0] = lo;
        pack_hl(o[nt][2] * inv1, o[nt][3] * inv1, hi, lo);
        const size_t p1 = (size_t)(b * 2048 + r0 + 8) * 1024 + c0 + nt * 8;
        *(uint32_t*)&g_ctxh[p1] = hi;
        *(uint32_t*)&g_ctxl[p1] = lo;
    }
}

// ---------------------------------------------------------------------------
// Launch.  Input order (metadata): x, Wk, Wq, Wv, Wo, bo
// ---------------------------------------------------------------------------
extern "C" void kernel_launch(void* const* d_in, const int* in_sizes, int n_in,
                              void* d_out, int out_size)
{
    const float* x  = (const float*)d_in[0];
    const float* Wk = (const float*)d_in[1];
    const float* Wq = (const float*)d_in[2];
    const float* Wv = (const float*)d_in[3];
    const float* Wo = (const float*)d_in[4];
    const float* bo = (const float*)d_in[5];
    float* out = (float*)d_out;

    static bool attr_done = false;
    if (!attr_done) {
        cudaFuncSetAttribute(gemm_kernel<0>,
                             cudaFuncAttributeMaxDynamicSharedMemorySize, GEMM_DYN_SMEM);
        cudaFuncSetAttribute(gemm_kernel<1>,
                             cudaFuncAttributeMaxDynamicSharedMemorySize, GEMM_DYN_SMEM);
        cudaFuncSetAttribute(flash_mma_kernel,
                             cudaFuncAttributeMaxDynamicSharedMemorySize, FLASH_SMEM);
        attr_done = true;
    }

    // One split launch: 8192 (x) + 4 x 1024 (weights) blocks
    split_all_kernel<<<12288, 256>>>((const float4*)x, (const float4*)Wq,
                                     (const float4*)Wk, (const float4*)Wv,
                                     (const float4*)Wo);

    // QKV projection: M=8192, virtual N = [Wq | Wk | Wv] = 3072
    dim3 g1(MTOT / 128, 3072 / 128);     // 64 x 24
    gemm_kernel<0><<<g1, 256, GEMM_DYN_SMEM>>>(nullptr, nullptr);

    dim3 g2(S_ / 128, B_ * H_);          // 16 x 64
    flash_mma_kernel<<<g2, 256, FLASH_SMEM>>>();

    // Output projection: M=8192, N=1024 (+ bias)
    dim3 g3(MTOT / 128, 1024 / 128);     // 64 x 8
    gemm_kernel<1><<<g3, 256, GEMM_DYN_SMEM>>>(bo, out);
}

// round 8
// speedup vs baseline: 1.2523x; 1.0507x over previous
#include <cuda_runtime.h>
#include <cuda_bf16.h>
#include <stdint.h>
#include <string.h>

// Problem constants
#define B_ 4
#define S_ 2048
#define D_ 1024
#define H_ 16
#define HS_ 64
#define MTOT (B_ * S_)   // 8192

// ---------------------------------------------------------------------------
// Pre-split bf16 hi/lo scratch (static device arrays — no allocation allowed)
// ---------------------------------------------------------------------------
__device__ __nv_bfloat16 g_xh[(size_t)MTOT * D_], g_xl[(size_t)MTOT * D_];
__device__ __nv_bfloat16 g_wqh[(size_t)D_ * D_], g_wql[(size_t)D_ * D_];
__device__ __nv_bfloat16 g_wkh[(size_t)D_ * D_], g_wkl[(size_t)D_ * D_];
__device__ __nv_bfloat16 g_wvh[(size_t)D_ * D_], g_wvl[(size_t)D_ * D_];
__device__ __nv_bfloat16 g_woh[(size_t)D_ * D_], g_wol[(size_t)D_ * D_];
// q,k,v: all [bh][s][hs] (q pre-scaled by 0.125 * log2(e))
__device__ __nv_bfloat16 g_qh[(size_t)64 * S_ * HS_], g_ql[(size_t)64 * S_ * HS_];
__device__ __nv_bfloat16 g_kh[(size_t)64 * S_ * HS_], g_kl[(size_t)64 * S_ * HS_];
__device__ __nv_bfloat16 g_vh[(size_t)64 * S_ * HS_], g_vl[(size_t)64 * S_ * HS_];
__device__ __nv_bfloat16 g_ctxh[(size_t)MTOT * D_], g_ctxl[(size_t)MTOT * D_];

// ---------------------------------------------------------------------------
// PTX helpers (arch-portable: sm_80+, valid on compute_103)
// ---------------------------------------------------------------------------
__device__ __forceinline__ uint32_t smem_u32(const void* p) {
    uint32_t a;
    asm("{ .reg .u64 t; cvta.to.shared.u64 t, %1; cvt.u32.u64 %0, t; }"
        : "=r"(a) : "l"(p));
    return a;
}

__device__ __forceinline__ float fast_exp2(float x) {
    float y;
    asm("ex2.approx.ftz.f32 %0, %1;" : "=f"(y) : "f"(x));
    return y;
}

#define CP_ASYNC16(dst, src) \
    asm volatile("cp.async.cg.shared.global [%0], [%1], 16;" \
        :: "r"(dst), "l"(src))
#define CP_COMMIT() asm volatile("cp.async.commit_group;" ::: "memory")
#define CP_WAIT(n)  asm volatile("cp.async.wait_group %0;" :: "n"(n) : "memory")

#define LDSM_X4(R, ADDR) \
    asm volatile("ldmatrix.sync.aligned.m8n8.x4.shared.b16 {%0,%1,%2,%3}, [%4];" \
        : "=r"((R)[0]), "=r"((R)[1]), "=r"((R)[2]), "=r"((R)[3]) : "r"(ADDR))

#define LDSM_X4_T(R, ADDR) \
    asm volatile("ldmatrix.sync.aligned.m8n8.x4.trans.shared.b16 {%0,%1,%2,%3}, [%4];" \
        : "=r"((R)[0]), "=r"((R)[1]), "=r"((R)[2]), "=r"((R)[3]) : "r"(ADDR))

#define MMA16816(C, A, B0, B1) \
    asm volatile("mma.sync.aligned.m16n8k16.row.col.f32.bf16.bf16.f32 " \
        "{%0,%1,%2,%3}, {%4,%5,%6,%7}, {%8,%9}, {%0,%1,%2,%3};" \
        : "+f"((C)[0]), "+f"((C)[1]), "+f"((C)[2]), "+f"((C)[3]) \
        : "r"((A)[0]), "r"((A)[1]), "r"((A)[2]), "r"((A)[3]), \
          "r"((B0)), "r"((B1)))

// Pack two floats into bf16x2 (hi) and residual bf16x2 (lo)
__device__ __forceinline__ void pack_hl(float a, float b,
                                        uint32_t& hi, uint32_t& lo) {
    __nv_bfloat162 h = __float22bfloat162_rn(make_float2(a, b));
    float2 f = __bfloat1622float2(h);
    __nv_bfloat162 l = __float22bfloat162_rn(make_float2(a - f.x, b - f.y));
    memcpy(&hi, &h, 4);
    memcpy(&lo, &l, 4);
}

// ---------------------------------------------------------------------------
// Combined split kernel: fp32 -> bf16 hi/lo for x + 4 weights, one launch.
// ---------------------------------------------------------------------------
__global__ __launch_bounds__(256, 4) void split_all_kernel(
    const float4* __restrict__ x,  const float4* __restrict__ Wq,
    const float4* __restrict__ Wk, const float4* __restrict__ Wv,
    const float4* __restrict__ Wo)
{
    const int bid = blockIdx.x;
    const float4* src;
    uint2 *dh, *dl;
    int base;
    if (bid < 8192)      { src = x;  dh = (uint2*)g_xh;  dl = (uint2*)g_xl;  base = bid; }
    else if (bid < 9216) { src = Wq; dh = (uint2*)g_wqh; dl = (uint2*)g_wql; base = bid - 8192; }
    else if (bid < 10240){ src = Wk; dh = (uint2*)g_wkh; dl = (uint2*)g_wkl; base = bid - 9216; }
    else if (bid < 11264){ src = Wv; dh = (uint2*)g_wvh; dl = (uint2*)g_wvl; base = bid - 10240; }
    else                 { src = Wo; dh = (uint2*)g_woh; dl = (uint2*)g_wol; base = bid - 11264; }
    const int i = base * 256 + threadIdx.x;
    float4 v = src[i];
    __nv_bfloat162 h01 = __float22bfloat162_rn(make_float2(v.x, v.y));
    __nv_bfloat162 h23 = __float22bfloat162_rn(make_float2(v.z, v.w));
    float2 f01 = __bfloat1622float2(h01);
    float2 f23 = __bfloat1622float2(h23);
    __nv_bfloat162 l01 = __float22bfloat162_rn(make_float2(v.x - f01.x, v.y - f01.y));
    __nv_bfloat162 l23 = __float22bfloat162_rn(make_float2(v.z - f23.x, v.w - f23.y));
    uint2 hv, lv;
    memcpy(&hv.x, &h01, 4); memcpy(&hv.y, &h23, 4);
    memcpy(&lv.x, &l01, 4); memcpy(&lv.y, &l23, 4);
    dh[i] = hv;
    dl[i] = lv;
}

// ---------------------------------------------------------------------------
// Split-bf16 GEMM: 128 threads, 4 warps (2x2), warp tile 64x64 (CUTLASS-style).
// CTA 128x128, BK=32, 3-stage cp.async, swizzled smem, 2 CTAs/SM.
// 192 MMAs per warp between barriers (2x the old 2x4 layout).
// ---------------------------------------------------------------------------
#define GTILE 16384u
#define GSTAGE 32768u
#define GEMM_DYN_SMEM (3 * 32768)

template<int MODE>
__global__ __launch_bounds__(128, 2) void gemm_kernel(
    const float* __restrict__ bo, float* __restrict__ outp)
{
    extern __shared__ char smem[];
    const int tid  = threadIdx.x;
    const int lane = tid & 31;
    const int wid  = tid >> 5;
    const int wm   = (wid & 1) * 64;
    const int wn   = (wid >> 1) * 64;
    const int m0   = blockIdx.x * 128;
    const int n0   = blockIdx.y * 128;

    const __nv_bfloat16 *Ah, *Al, *Bh, *Bl;
    int nbase;
    if (MODE == 0) {
        Ah = g_xh; Al = g_xl;
        const int mat = n0 >> 10;
        Bh = (mat == 0) ? g_wqh : ((mat == 1) ? g_wkh : g_wvh);
        Bl = (mat == 0) ? g_wql : ((mat == 1) ? g_wkl : g_wvl);
        nbase = n0 & 1023;
    } else {
        Ah = g_ctxh; Al = g_ctxl; Bh = g_woh; Bl = g_wol;
        nbase = n0;
    }

    // Loader: per thread, row = tid>>3 (stride 16 over i), col = tid&7.
    // col<4 -> hi buffer, col>=4 -> lo buffer; k offset = (col&3)*8 elems.
    const int lrow = tid >> 3, lcol = tid & 7;
    const char* aB = (const char*)(((lcol < 4) ? Ah : Al)
                     + (size_t)(m0 + lrow) * 1024 + (lcol & 3) * 8);
    const char* bB = (const char*)(((lcol < 4) ? Bh : Bl)
                     + (size_t)(nbase + lrow) * 1024 + (lcol & 3) * 8);
    const uint32_t da = (uint32_t)(lrow * 128) + (uint32_t)((lcol ^ (lrow & 7)) << 4);
    const uint32_t db = GTILE + da;
    const uint32_t s0 = smem_u32(smem);

    // prologue: stages 0, 1
#pragma unroll
    for (int s = 0; s < 2; s++) {
        const uint32_t sb = s0 + (uint32_t)s * GSTAGE;
#pragma unroll
        for (int i = 0; i < 8; i++) {
            CP_ASYNC16(sb + da + i * 2048, aB + s * 64 + (size_t)i * 32768);
            CP_ASYNC16(sb + db + i * 2048, bB + s * 64 + (size_t)i * 32768);
        }
        CP_COMMIT();
    }

    float c[4][8][4];
#pragma unroll
    for (int i = 0; i < 4; i++)
#pragma unroll
        for (int j = 0; j < 8; j++)
#pragma unroll
            for (int q = 0; q < 4; q++) c[i][j][q] = 0.0f;

    const int l7 = lane & 7;
    const uint32_t arowoff = (uint32_t)((wm + (lane & 15)) * 128);
    const uint32_t browoff = (uint32_t)((wn + (lane & 7) + ((lane >> 4) & 1) * 8) * 128);

    int sb_idx = 0;
    for (int s = 0; s < 32; s++) {
        if (s == 31) { CP_WAIT(0); } else { CP_WAIT(1); }
        __syncthreads();
        if (s + 2 < 32) {
            const int nb = (sb_idx + 2 >= 3) ? sb_idx - 1 : sb_idx + 2;
            const uint32_t sb2 = s0 + (uint32_t)nb * GSTAGE;
#pragma unroll
            for (int i = 0; i < 8; i++) {
                CP_ASYNC16(sb2 + da + i * 2048, aB + (s + 2) * 64 + (size_t)i * 32768);
                CP_ASYNC16(sb2 + db + i * 2048, bB + (s + 2) * 64 + (size_t)i * 32768);
            }
            CP_COMMIT();
        }

        const uint32_t sb = s0 + (uint32_t)sb_idx * GSTAGE;
        const uint32_t sA = sb + arowoff;
        const uint32_t sB = sb + GTILE + browoff;
#pragma unroll
        for (int kk = 0; kk < 2; kk++) {
            const uint32_t offA = (uint32_t)(((kk * 2 + (lane >> 4)) ^ l7) << 4);
            const uint32_t offB = (uint32_t)(((kk * 2 + ((lane >> 3) & 1)) ^ l7) << 4);
            uint32_t bh4[4][4], bl4[4][4], ah[4][4], al[4][4];
#pragma unroll
            for (int g = 0; g < 4; g++) {
                LDSM_X4(bh4[g], sB + g * 2048 + offB);
                LDSM_X4(bl4[g], sB + g * 2048 + (offB ^ 64u));
            }
#pragma unroll
            for (int mi = 0; mi < 4; mi++) {
                LDSM_X4(ah[mi], sA + mi * 2048 + offA);
                LDSM_X4(al[mi], sA + mi * 2048 + (offA ^ 64u));
            }
#pragma unroll
            for (int mi = 0; mi < 4; mi++)
#pragma unroll
                for (int g = 0; g < 4; g++) {
                    MMA16816(c[mi][2 * g],     ah[mi], bh4[g][0], bh4[g][1]);
                    MMA16816(c[mi][2 * g + 1], ah[mi], bh4[g][2], bh4[g][3]);
                    MMA16816(c[mi][2 * g],     ah[mi], bl4[g][0], bl4[g][1]);
                    MMA16816(c[mi][2 * g + 1], ah[mi], bl4[g][2], bl4[g][3]);
                    MMA16816(c[mi][2 * g],     al[mi], bh4[g][0], bh4[g][1]);
                    MMA16816(c[mi][2 * g + 1], al[mi], bh4[g][2], bh4[g][3]);
                }
        }
        sb_idx = (sb_idx + 1 >= 3) ? 0 : sb_idx + 1;
    }

    // ---- epilogue (coalesced) ----
    const int mrow = lane >> 2;
    const int ncol = (lane & 3) * 2;
#pragma unroll
    for (int mi = 0; mi < 4; mi++)
#pragma unroll
        for (int nj = 0; nj < 8; nj++) {
            const int col = n0 + wn + nj * 8 + ncol;
#pragma unroll
            for (int half = 0; half < 2; half++) {
                const int m = m0 + wm + mi * 16 + mrow + half * 8;
                const float v0 = c[mi][nj][half * 2 + 0];
                const float v1 = c[mi][nj][half * 2 + 1];
                if (MODE == 0) {
                    const int mat = col >> 10;
                    const int loc = col & 1023;
                    const int h = loc >> 6, hs = loc & 63;
                    const int b = m >> 11, si = m & 2047;
                    // q scaled by 0.125 * log2(e) for exp2-domain softmax
                    const float sc = (mat == 0) ? 0.18033688f : 1.0f;
                    uint32_t hi, lo;
                    pack_hl(v0 * sc, v1 * sc, hi, lo);
                    __nv_bfloat16* dsth = (mat == 0) ? g_qh : ((mat == 1) ? g_kh : g_vh);
                    __nv_bfloat16* dstl = (mat == 0) ? g_ql : ((mat == 1) ? g_kl : g_vl);
                    const size_t p0 = (((size_t)(b * 16 + h)) * 2048 + si) * 64 + hs;
                    *(uint32_t*)&dsth[p0] = hi;
                    *(uint32_t*)&dstl[p0] = lo;
                } else {
                    *(float2*)&outp[(size_t)m * 1024 + col] =
                        make_float2(v0 + bo[col], v1 + bo[col + 1]);
                }
            }
        }
}

// ---------------------------------------------------------------------------
// Flash attention: swizzled smem (96KB, 2 CTAs/SM), cp.async K/V dbl-buffer,
// V via ldmatrix.trans, softmax in exp2 domain (Q pre-scaled by log2e/8).
// ---------------------------------------------------------------------------
#define FTILE 8192u
#define FSTAGE 32768u
#define FLASH_SMEM (32768 + 2 * 32768)   // 98304

__global__ __launch_bounds__(256, 2) void flash_mma_kernel()
{
    extern __shared__ char fsm[];
    const uint32_t s0 = smem_u32(fsm);
    const uint32_t oQl = 16384u, oKV = 32768u;

    const int tid = threadIdx.x, lane = tid & 31, wid = tid >> 5;
    const int qt = (int)gridDim.x - 1 - (int)blockIdx.x;   // heavy first
    const int bh = blockIdx.y;
    const int wm = wid * 16;
    const int l7 = lane & 7;

    // ---- issue Q (hi/lo) via cp.async ----
#pragma unroll
    for (int i = 0; i < 8; i++) {
        const int tile = i >> 2;
        const int cc   = (i & 3) * 256 + tid;
        const int row  = cc >> 3, col = cc & 7;
        const __nv_bfloat16* qsrc = ((tile == 0) ? g_qh : g_ql)
            + (size_t)bh * 131072 + (size_t)(qt * 128 + row) * 64 + col * 8;
        CP_ASYNC16(s0 + (uint32_t)tile * 16384u + (uint32_t)row * 128u
                       + (uint32_t)((col ^ (row & 7)) << 4), qsrc);
    }
    CP_COMMIT();

    // ---- KV loader: 4 tiles (Kh,Kl,Vh,Vl), all [64 keys][64 hs] ----
    const char* skv[8];
    uint32_t dkv[8];
#pragma unroll
    for (int i = 0; i < 8; i++) {
        const int tile = i >> 1;
        const int cc   = (i & 1) * 256 + tid;
        const int row  = cc >> 3, col = cc & 7;
        const __nv_bfloat16* bp =
            ((tile == 0) ? g_kh : (tile == 1) ? g_kl : (tile == 2) ? g_vh : g_vl)
            + (size_t)bh * 131072 + (size_t)row * 64 + col * 8;
        skv[i] = (const char*)bp;
        dkv[i] = oKV + (uint32_t)tile * FTILE + (uint32_t)row * 128u
               + (uint32_t)((col ^ (row & 7)) << 4);
    }
#pragma unroll
    for (int i = 0; i < 8; i++) CP_ASYNC16(s0 + dkv[i], skv[i]);
    CP_COMMIT();

    float o[8][4];
#pragma unroll
    for (int i = 0; i < 8; i++)
#pragma unroll
        for (int j = 0; j < 4; j++) o[i][j] = 0.0f;
    float mrow[2] = {-1e30f, -1e30f}, lrow[2] = {0.0f, 0.0f};

    const uint32_t aQ  = (uint32_t)((wm + (lane & 15)) * 128);
    const uint32_t bKV = (uint32_t)(((lane & 7) + ((lane >> 4) & 1) * 8) * 128);
    const int vrowb = (lane & 7) + 8 * ((lane >> 3) & 1);
    const int vsel  = (lane >> 4) & 1;

    const int nkt = 2 * qt + 2;
    for (int kt = 0; kt < nkt; kt++) {
        CP_WAIT(0);
        __syncthreads();
        if (kt + 1 < nkt) {
            const uint32_t st2 = (uint32_t)((kt + 1) & 1) * FSTAGE;
#pragma unroll
            for (int i = 0; i < 8; i++)
                CP_ASYNC16(s0 + st2 + dkv[i], skv[i] + (size_t)(kt + 1) * 8192);
            CP_COMMIT();
        }

        const uint32_t ss  = (uint32_t)(kt & 1) * FSTAGE;
        const uint32_t sKh = s0 + ss + oKV + bKV;
        const uint32_t sV  = s0 + ss + oKV + 2 * FTILE;

        // ---- S_log2 = Qs @ K^T (3-term split; Q pre-scaled by log2e/8) ----
        float sc[8][4];
#pragma unroll
        for (int i = 0; i < 8; i++)
#pragma unroll
            for (int j = 0; j < 4; j++) sc[i][j] = 0.0f;
#pragma unroll
        for (int kk = 0; kk < 4; kk++) {
            const uint32_t offA = (uint32_t)(((kk * 2 + (lane >> 4)) ^ l7) << 4);
            const uint32_t offB = (uint32_t)(((kk * 2 + ((lane >> 3) & 1)) ^ l7) << 4);
            uint32_t ah[4], al[4];
            LDSM_X4(ah, s0 + aQ + offA);
            LDSM_X4(al, s0 + oQl + aQ + offA);
#pragma unroll
            for (int nt2 = 0; nt2 < 4; nt2++) {
                uint32_t bh4[4], bl4[4];
                LDSM_X4(bh4, sKh + nt2 * 2048 + offB);
                LDSM_X4(bl4, sKh + FTILE + nt2 * 2048 + offB);
                MMA16816(sc[2 * nt2],     ah, bh4[0], bh4[1]);
                MMA16816(sc[2 * nt2 + 1], ah, bh4[2], bh4[3]);
                MMA16816(sc[2 * nt2],     ah, bl4[0], bl4[1]);
                MMA16816(sc[2 * nt2 + 1], ah, bl4[2], bl4[3]);
                MMA16816(sc[2 * nt2],     al, bh4[0], bh4[1]);
                MMA16816(sc[2 * nt2 + 1], al, bh4[2], bh4[3]);
            }
        }

        // ---- causal mask ----
        if (kt >= 2 * qt) {
            const int baser = qt * 128 + wm + (lane >> 2);
            const int baseg = kt * 64 + ((lane & 3) << 1);
#pragma unroll
            for (int nt = 0; nt < 8; nt++)
#pragma unroll
                for (int j = 0; j < 4; j++) {
                    const int row = baser + ((j >> 1) << 3);
                    const int g   = baseg + nt * 8 + (j & 1);
                    if (g > row) sc[nt][j] = -1e30f;
                }
        }

        // ---- online softmax (exp2 domain) ----
#pragma unroll
        for (int hh = 0; hh < 2; hh++) {
            float rm = -1e30f;
#pragma unroll
            for (int nt = 0; nt < 8; nt++)
                rm = fmaxf(rm, fmaxf(sc[nt][2 * hh], sc[nt][2 * hh + 1]));
            rm = fmaxf(rm, __shfl_xor_sync(0xffffffffu, rm, 1));
            rm = fmaxf(rm, __shfl_xor_sync(0xffffffffu, rm, 2));
            const float mnew = fmaxf(mrow[hh], rm);
            const float corr = fast_exp2(mrow[hh] - mnew);
            mrow[hh] = mnew;
            float rs = 0.0f;
#pragma unroll
            for (int nt = 0; nt < 8; nt++) {
                sc[nt][2 * hh]     = fast_exp2(sc[nt][2 * hh] - mnew);
                sc[nt][2 * hh + 1] = fast_exp2(sc[nt][2 * hh + 1] - mnew);
                rs += sc[nt][2 * hh] + sc[nt][2 * hh + 1];
            }
            rs += __shfl_xor_sync(0xffffffffu, rs, 1);
            rs += __shfl_xor_sync(0xffffffffu, rs, 2);
            lrow[hh] = lrow[hh] * corr + rs;
#pragma unroll
            for (int nt = 0; nt < 8; nt++) {
                o[nt][2 * hh]     *= corr;
                o[nt][2 * hh + 1] *= corr;
            }
        }

        // ---- O += P @ V (3-term split; V via trans-ldmatrix) ----
#pragma unroll
        for (int t = 0; t < 4; t++) {
            const int vrow = t * 16 + vrowb;
            uint32_t ap[4], alp[4];
            pack_hl(sc[2 * t][0],     sc[2 * t][1],     ap[0], alp[0]);
            pack_hl(sc[2 * t][2],     sc[2 * t][3],     ap[1], alp[1]);
            pack_hl(sc[2 * t + 1][0], sc[2 * t + 1][1], ap[2], alp[2]);
            pack_hl(sc[2 * t + 1][2], sc[2 * t + 1][3], ap[3], alp[3]);
#pragma unroll
            for (int nt2 = 0; nt2 < 4; nt2++) {
                const int col16 = nt2 * 2 + vsel;
                const uint32_t vaddr = (uint32_t)(vrow * 128)
                                     + (uint32_t)((col16 ^ (vrow & 7)) << 4);
                uint32_t bh4[4], bl4[4];
                LDSM_X4_T(bh4, sV + vaddr);
                LDSM_X4_T(bl4, sV + FTILE + vaddr);
                MMA16816(o[2 * nt2],     ap,  bh4[0], bh4[1]);
                MMA16816(o[2 * nt2 + 1], ap,  bh4[2], bh4[3]);
                MMA16816(o[2 * nt2],     ap,  bl4[0], bl4[1]);
                MMA16816(o[2 * nt2 + 1], ap,  bl4[2], bl4[3]);
                MMA16816(o[2 * nt2],     alp, bh4[0], bh4[1]);
                MMA16816(o[2 * nt2 + 1], alp, bh4[2], bh4[3]);
            }
        }
    }

    // ---- epilogue: normalize, split to ctx hi/lo bf16 ----
    const float inv0 = 1.0f / lrow[0];
    const float inv1 = 1.0f / lrow[1];
    const int b = bh >> 4, h = bh & 15;
    const int r0 = qt * 128 + wm + (lane >> 2);
    const int c0 = h * 64 + ((lane & 3) << 1);
#pragma unroll
    for (int nt = 0; nt < 8; nt++) {
        uint32_t hi, lo;
        pack_hl(o[nt][0] * inv0, o[nt][1] * inv0, hi, lo);
        const size_t p0 = (size_t)(b * 2048 + r0) * 1024 + c0 + nt * 8;
        *(uint32_t*)&g_ctxh[p0] = hi;
        *(uint32_t*)&g_ctxl[p0] = lo;
        pack_hl(o[nt][2] * inv1, o[nt][3] * inv1, hi, lo);
        const size_t p1 = (size_t)(b * 2048 + r0 + 8) * 1024 + c0 + nt * 8;
        *(uint32_t*)&g_ctxh[p1] = hi;
        *(uint32_t*)&g_ctxl[p1] = lo;
    }
}

// ---------------------------------------------------------------------------
// Launch.  Input order (metadata): x, Wk, Wq, Wv, Wo, bo
// ---------------------------------------------------------------------------
extern "C" void kernel_launch(void* const* d_in, const int* in_sizes, int n_in,
                              void* d_out, int out_size)
{
    const float* x  = (const float*)d_in[0];
    const float* Wk = (const float*)d_in[1];
    const float* Wq = (const float*)d_in[2];
    const float* Wv = (const float*)d_in[3];
    const float* Wo = (const float*)d_in[4];
    const float* bo = (const float*)d_in[5];
    float* out = (float*)d_out;

    static bool attr_done = false;
    if (!attr_done) {
        cudaFuncSetAttribute(gemm_kernel<0>,
                             cudaFuncAttributeMaxDynamicSharedMemorySize, GEMM_DYN_SMEM);
        cudaFuncSetAttribute(gemm_kernel<1>,
                             cudaFuncAttributeMaxDynamicSharedMemorySize, GEMM_DYN_SMEM);
        cudaFuncSetAttribute(flash_mma_kernel,
                             cudaFuncAttributeMaxDynamicSharedMemorySize, FLASH_SMEM);
        attr_done = true;
    }

    split_all_kernel<<<12288, 256>>>((const float4*)x, (const float4*)Wq,
                                     (const float4*)Wk, (const float4*)Wv,
                                     (const float4*)Wo);

    // QKV projection: M=8192, virtual N = [Wq | Wk | Wv] = 3072
    dim3 g1(MTOT / 128, 3072 / 128);     // 64 x 24, 128-thread CTAs
    gemm_kernel<0><<<g1, 128, GEMM_DYN_SMEM>>>(nullptr, nullptr);

    dim3 g2(S_ / 128, B_ * H_);          // 16 x 64
    flash_mma_kernel<<<g2, 256, FLASH_SMEM>>>();

    // Output projection: M=8192, N=1024 (+ bias)
    dim3 g3(MTOT / 128, 1024 / 128);     // 64 x 8
    gemm_kernel<1><<<g3, 128, GEMM_DYN_SMEM>>>(bo, out);
}

// round 9
// speedup vs baseline: 1.2622x; 1.0079x over previous
#include <cuda_runtime.h>
#include <cuda_bf16.h>
#include <stdint.h>
#include <string.h>

// Problem constants
#define B_ 4
#define S_ 2048
#define D_ 1024
#define H_ 16
#define HS_ 64
#define MTOT (B_ * S_)   // 8192

// ---------------------------------------------------------------------------
// Pre-split bf16 hi/lo scratch (static device arrays — no allocation allowed)
// ---------------------------------------------------------------------------
__device__ __nv_bfloat16 g_xh[(size_t)MTOT * D_], g_xl[(size_t)MTOT * D_];
__device__ __nv_bfloat16 g_wqh[(size_t)D_ * D_], g_wql[(size_t)D_ * D_];
__device__ __nv_bfloat16 g_wkh[(size_t)D_ * D_], g_wkl[(size_t)D_ * D_];
__device__ __nv_bfloat16 g_wvh[(size_t)D_ * D_], g_wvl[(size_t)D_ * D_];
__device__ __nv_bfloat16 g_woh[(size_t)D_ * D_], g_wol[(size_t)D_ * D_];
// q,k,v: all [bh][s][hs] (q pre-scaled by 0.125 * log2(e))
__device__ __nv_bfloat16 g_qh[(size_t)64 * S_ * HS_], g_ql[(size_t)64 * S_ * HS_];
__device__ __nv_bfloat16 g_kh[(size_t)64 * S_ * HS_], g_kl[(size_t)64 * S_ * HS_];
__device__ __nv_bfloat16 g_vh[(size_t)64 * S_ * HS_], g_vl[(size_t)64 * S_ * HS_];
__device__ __nv_bfloat16 g_ctxh[(size_t)MTOT * D_], g_ctxl[(size_t)MTOT * D_];

// ---------------------------------------------------------------------------
// PTX helpers (arch-portable: sm_80+, valid on compute_103)
// ---------------------------------------------------------------------------
__device__ __forceinline__ uint32_t smem_u32(const void* p) {
    uint32_t a;
    asm("{ .reg .u64 t; cvta.to.shared.u64 t, %1; cvt.u32.u64 %0, t; }"
        : "=r"(a) : "l"(p));
    return a;
}

__device__ __forceinline__ float fast_exp2(float x) {
    float y;
    asm("ex2.approx.ftz.f32 %0, %1;" : "=f"(y) : "f"(x));
    return y;
}

#define CP_ASYNC16(dst, src) \
    asm volatile("cp.async.cg.shared.global [%0], [%1], 16;" \
        :: "r"(dst), "l"(src))
#define CP_COMMIT() asm volatile("cp.async.commit_group;" ::: "memory")
#define CP_WAIT(n)  asm volatile("cp.async.wait_group %0;" :: "n"(n) : "memory")

#define LDSM_X4(R, ADDR) \
    asm volatile("ldmatrix.sync.aligned.m8n8.x4.shared.b16 {%0,%1,%2,%3}, [%4];" \
        : "=r"((R)[0]), "=r"((R)[1]), "=r"((R)[2]), "=r"((R)[3]) : "r"(ADDR))

#define LDSM_X4_T(R, ADDR) \
    asm volatile("ldmatrix.sync.aligned.m8n8.x4.trans.shared.b16 {%0,%1,%2,%3}, [%4];" \
        : "=r"((R)[0]), "=r"((R)[1]), "=r"((R)[2]), "=r"((R)[3]) : "r"(ADDR))

#define MMA16816(C, A, B0, B1) \
    asm volatile("mma.sync.aligned.m16n8k16.row.col.f32.bf16.bf16.f32 " \
        "{%0,%1,%2,%3}, {%4,%5,%6,%7}, {%8,%9}, {%0,%1,%2,%3};" \
        : "+f"((C)[0]), "+f"((C)[1]), "+f"((C)[2]), "+f"((C)[3]) \
        : "r"((A)[0]), "r"((A)[1]), "r"((A)[2]), "r"((A)[3]), \
          "r"((B0)), "r"((B1)))

// Pack two floats into bf16x2 (hi) and residual bf16x2 (lo)
__device__ __forceinline__ void pack_hl(float a, float b,
                                        uint32_t& hi, uint32_t& lo) {
    __nv_bfloat162 h = __float22bfloat162_rn(make_float2(a, b));
    float2 f = __bfloat1622float2(h);
    __nv_bfloat162 l = __float22bfloat162_rn(make_float2(a - f.x, b - f.y));
    memcpy(&hi, &h, 4);
    memcpy(&lo, &l, 4);
}

// ---------------------------------------------------------------------------
// Combined split kernel: fp32 -> bf16 hi/lo for x + 4 weights, one launch.
// ---------------------------------------------------------------------------
__global__ __launch_bounds__(256, 4) void split_all_kernel(
    const float4* __restrict__ x,  const float4* __restrict__ Wq,
    const float4* __restrict__ Wk, const float4* __restrict__ Wv,
    const float4* __restrict__ Wo)
{
    const int bid = blockIdx.x;
    const float4* src;
    uint2 *dh, *dl;
    int base;
    if (bid < 8192)      { src = x;  dh = (uint2*)g_xh;  dl = (uint2*)g_xl;  base = bid; }
    else if (bid < 9216) { src = Wq; dh = (uint2*)g_wqh; dl = (uint2*)g_wql; base = bid - 8192; }
    else if (bid < 10240){ src = Wk; dh = (uint2*)g_wkh; dl = (uint2*)g_wkl; base = bid - 9216; }
    else if (bid < 11264){ src = Wv; dh = (uint2*)g_wvh; dl = (uint2*)g_wvl; base = bid - 10240; }
    else                 { src = Wo; dh = (uint2*)g_woh; dl = (uint2*)g_wol; base = bid - 11264; }
    const int i = base * 256 + threadIdx.x;
    float4 v = src[i];
    __nv_bfloat162 h01 = __float22bfloat162_rn(make_float2(v.x, v.y));
    __nv_bfloat162 h23 = __float22bfloat162_rn(make_float2(v.z, v.w));
    float2 f01 = __bfloat1622float2(h01);
    float2 f23 = __bfloat1622float2(h23);
    __nv_bfloat162 l01 = __float22bfloat162_rn(make_float2(v.x - f01.x, v.y - f01.y));
    __nv_bfloat162 l23 = __float22bfloat162_rn(make_float2(v.z - f23.x, v.w - f23.y));
    uint2 hv, lv;
    memcpy(&hv.x, &h01, 4); memcpy(&hv.y, &h23, 4);
    memcpy(&lv.x, &l01, 4); memcpy(&lv.y, &l23, 4);
    dh[i] = hv;
    dl[i] = lv;
}

// ---------------------------------------------------------------------------
// Split-bf16 GEMM: 128 threads, 4 warps (2x2), warp tile 64x64.
// CTA 128x128, BK=32, 3-stage cp.async, swizzled smem, 2 CTAs/SM.
// ---------------------------------------------------------------------------
#define GTILE 16384u
#define GSTAGE 32768u
#define GEMM_DYN_SMEM (3 * 32768)

template<int MODE>
__global__ __launch_bounds__(128, 2) void gemm_kernel(
    const float* __restrict__ bo, float* __restrict__ outp)
{
    extern __shared__ char smem[];
    const int tid  = threadIdx.x;
    const int lane = tid & 31;
    const int wid  = tid >> 5;
    const int wm   = (wid & 1) * 64;
    const int wn   = (wid >> 1) * 64;
    const int m0   = blockIdx.x * 128;
    const int n0   = blockIdx.y * 128;

    const __nv_bfloat16 *Ah, *Al, *Bh, *Bl;
    int nbase;
    if (MODE == 0) {
        Ah = g_xh; Al = g_xl;
        const int mat = n0 >> 10;
        Bh = (mat == 0) ? g_wqh : ((mat == 1) ? g_wkh : g_wvh);
        Bl = (mat == 0) ? g_wql : ((mat == 1) ? g_wkl : g_wvl);
        nbase = n0 & 1023;
    } else {
        Ah = g_ctxh; Al = g_ctxl; Bh = g_woh; Bl = g_wol;
        nbase = n0;
    }

    const int lrow = tid >> 3, lcol = tid & 7;
    const char* aB = (const char*)(((lcol < 4) ? Ah : Al)
                     + (size_t)(m0 + lrow) * 1024 + (lcol & 3) * 8);
    const char* bB = (const char*)(((lcol < 4) ? Bh : Bl)
                     + (size_t)(nbase + lrow) * 1024 + (lcol & 3) * 8);
    const uint32_t da = (uint32_t)(lrow * 128) + (uint32_t)((lcol ^ (lrow & 7)) << 4);
    const uint32_t db = GTILE + da;
    const uint32_t s0 = smem_u32(smem);

#pragma unroll
    for (int s = 0; s < 2; s++) {
        const uint32_t sb = s0 + (uint32_t)s * GSTAGE;
#pragma unroll
        for (int i = 0; i < 8; i++) {
            CP_ASYNC16(sb + da + i * 2048, aB + s * 64 + (size_t)i * 32768);
            CP_ASYNC16(sb + db + i * 2048, bB + s * 64 + (size_t)i * 32768);
        }
        CP_COMMIT();
    }

    float c[4][8][4];
#pragma unroll
    for (int i = 0; i < 4; i++)
#pragma unroll
        for (int j = 0; j < 8; j++)
#pragma unroll
            for (int q = 0; q < 4; q++) c[i][j][q] = 0.0f;

    const int l7 = lane & 7;
    const uint32_t arowoff = (uint32_t)((wm + (lane & 15)) * 128);
    const uint32_t browoff = (uint32_t)((wn + (lane & 7) + ((lane >> 4) & 1) * 8) * 128);

    int sb_idx = 0;
    for (int s = 0; s < 32; s++) {
        if (s == 31) { CP_WAIT(0); } else { CP_WAIT(1); }
        __syncthreads();
        if (s + 2 < 32) {
            const int nb = (sb_idx + 2 >= 3) ? sb_idx - 1 : sb_idx + 2;
            const uint32_t sb2 = s0 + (uint32_t)nb * GSTAGE;
#pragma unroll
            for (int i = 0; i < 8; i++) {
                CP_ASYNC16(sb2 + da + i * 2048, aB + (s + 2) * 64 + (size_t)i * 32768);
                CP_ASYNC16(sb2 + db + i * 2048, bB + (s + 2) * 64 + (size_t)i * 32768);
            }
            CP_COMMIT();
        }

        const uint32_t sb = s0 + (uint32_t)sb_idx * GSTAGE;
        const uint32_t sA = sb + arowoff;
        const uint32_t sB = sb + GTILE + browoff;
#pragma unroll
        for (int kk = 0; kk < 2; kk++) {
            const uint32_t offA = (uint32_t)(((kk * 2 + (lane >> 4)) ^ l7) << 4);
            const uint32_t offB = (uint32_t)(((kk * 2 + ((lane >> 3) & 1)) ^ l7) << 4);
            uint32_t bh4[4][4], bl4[4][4], ah[4][4], al[4][4];
#pragma unroll
            for (int g = 0; g < 4; g++) {
                LDSM_X4(bh4[g], sB + g * 2048 + offB);
                LDSM_X4(bl4[g], sB + g * 2048 + (offB ^ 64u));
            }
#pragma unroll
            for (int mi = 0; mi < 4; mi++) {
                LDSM_X4(ah[mi], sA + mi * 2048 + offA);
                LDSM_X4(al[mi], sA + mi * 2048 + (offA ^ 64u));
            }
#pragma unroll
            for (int mi = 0; mi < 4; mi++)
#pragma unroll
                for (int g = 0; g < 4; g++) {
                    MMA16816(c[mi][2 * g],     ah[mi], bh4[g][0], bh4[g][1]);
                    MMA16816(c[mi][2 * g + 1], ah[mi], bh4[g][2], bh4[g][3]);
                    MMA16816(c[mi][2 * g],     ah[mi], bl4[g][0], bl4[g][1]);
                    MMA16816(c[mi][2 * g + 1], ah[mi], bl4[g][2], bl4[g][3]);
                    MMA16816(c[mi][2 * g],     al[mi], bh4[g][0], bh4[g][1]);
                    MMA16816(c[mi][2 * g + 1], al[mi], bh4[g][2], bh4[g][3]);
                }
        }
        sb_idx = (sb_idx + 1 >= 3) ? 0 : sb_idx + 1;
    }

    // ---- epilogue (coalesced) ----
    const int mrow = lane >> 2;
    const int ncol = (lane & 3) * 2;
#pragma unroll
    for (int mi = 0; mi < 4; mi++)
#pragma unroll
        for (int nj = 0; nj < 8; nj++) {
            const int col = n0 + wn + nj * 8 + ncol;
#pragma unroll
            for (int half = 0; half < 2; half++) {
                const int m = m0 + wm + mi * 16 + mrow + half * 8;
                const float v0 = c[mi][nj][half * 2 + 0];
                const float v1 = c[mi][nj][half * 2 + 1];
                if (MODE == 0) {
                    const int mat = col >> 10;
                    const int loc = col & 1023;
                    const int h = loc >> 6, hs = loc & 63;
                    const int b = m >> 11, si = m & 2047;
                    const float sc = (mat == 0) ? 0.18033688f : 1.0f;
                    uint32_t hi, lo;
                    pack_hl(v0 * sc, v1 * sc, hi, lo);
                    __nv_bfloat16* dsth = (mat == 0) ? g_qh : ((mat == 1) ? g_kh : g_vh);
                    __nv_bfloat16* dstl = (mat == 0) ? g_ql : ((mat == 1) ? g_kl : g_vl);
                    const size_t p0 = (((size_t)(b * 16 + h)) * 2048 + si) * 64 + hs;
                    *(uint32_t*)&dsth[p0] = hi;
                    *(uint32_t*)&dstl[p0] = lo;
                } else {
                    *(float2*)&outp[(size_t)m * 1024 + col] =
                        make_float2(v0 + bo[col], v1 + bo[col + 1]);
                }
            }
        }
}

// ---------------------------------------------------------------------------
// Flash attention: swizzled smem (96KB), cp.async K/V dbl-buffer,
// V via ldmatrix.trans, softmax in exp2 domain.
// ---------------------------------------------------------------------------
#define FTILE 8192u
#define FSTAGE 32768u
#define FLASH_SMEM (32768 + 2 * 32768)   // 98304

__global__ __launch_bounds__(256, 2) void flash_mma_kernel()
{
    extern __shared__ char fsm[];
    const uint32_t s0 = smem_u32(fsm);
    const uint32_t oQl = 16384u, oKV = 32768u;

    const int tid = threadIdx.x, lane = tid & 31, wid = tid >> 5;
    const int qt = (int)gridDim.x - 1 - (int)blockIdx.x;   // heavy first
    const int bh = blockIdx.y;
    const int wm = wid * 16;
    const int l7 = lane & 7;

#pragma unroll
    for (int i = 0; i < 8; i++) {
        const int tile = i >> 2;
        const int cc   = (i & 3) * 256 + tid;
        const int row  = cc >> 3, col = cc & 7;
        const __nv_bfloat16* qsrc = ((tile == 0) ? g_qh : g_ql)
            + (size_t)bh * 131072 + (size_t)(qt * 128 + row) * 64 + col * 8;
        CP_ASYNC16(s0 + (uint32_t)tile * 16384u + (uint32_t)row * 128u
                       + (uint32_t)((col ^ (row & 7)) << 4), qsrc);
    }
    CP_COMMIT();

    const char* skv[8];
    uint32_t dkv[8];
#pragma unroll
    for (int i = 0; i < 8; i++) {
        const int tile = i >> 1;
        const int cc   = (i & 1) * 256 + tid;
        const int row  = cc >> 3, col = cc & 7;
        const __nv_bfloat16* bp =
            ((tile == 0) ? g_kh : (tile == 1) ? g_kl : (tile == 2) ? g_vh : g_vl)
            + (size_t)bh * 131072 + (size_t)row * 64 + col * 8;
        skv[i] = (const char*)bp;
        dkv[i] = oKV + (uint32_t)tile * FTILE + (uint32_t)row * 128u
               + (uint32_t)((col ^ (row & 7)) << 4);
    }
#pragma unroll
    for (int i = 0; i < 8; i++) CP_ASYNC16(s0 + dkv[i], skv[i]);
    CP_COMMIT();

    float o[8][4];
#pragma unroll
    for (int i = 0; i < 8; i++)
#pragma unroll
        for (int j = 0; j < 4; j++) o[i][j] = 0.0f;
    float mrow[2] = {-1e30f, -1e30f}, lrow[2] = {0.0f, 0.0f};

    const uint32_t aQ  = (uint32_t)((wm + (lane & 15)) * 128);
    const uint32_t bKV = (uint32_t)(((lane & 7) + ((lane >> 4) & 1) * 8) * 128);
    const int vrowb = (lane & 7) + 8 * ((lane >> 3) & 1);
    const int vsel  = (lane >> 4) & 1;

    const int nkt = 2 * qt + 2;
    for (int kt = 0; kt < nkt; kt++) {
        CP_WAIT(0);
        __syncthreads();
        if (kt + 1 < nkt) {
            const uint32_t st2 = (uint32_t)((kt + 1) & 1) * FSTAGE;
#pragma unroll
            for (int i = 0; i < 8; i++)
                CP_ASYNC16(s0 + st2 + dkv[i], skv[i] + (size_t)(kt + 1) * 8192);
            CP_COMMIT();
        }

        const uint32_t ss  = (uint32_t)(kt & 1) * FSTAGE;
        const uint32_t sKh = s0 + ss + oKV + bKV;
        const uint32_t sV  = s0 + ss + oKV + 2 * FTILE;

        float sc[8][4];
#pragma unroll
        for (int i = 0; i < 8; i++)
#pragma unroll
            for (int j = 0; j < 4; j++) sc[i][j] = 0.0f;
#pragma unroll
        for (int kk = 0; kk < 4; kk++) {
            const uint32_t offA = (uint32_t)(((kk * 2 + (lane >> 4)) ^ l7) << 4);
            const uint32_t offB = (uint32_t)(((kk * 2 + ((lane >> 3) & 1)) ^ l7) << 4);
            uint32_t ah[4], al[4];
            LDSM_X4(ah, s0 + aQ + offA);
            LDSM_X4(al, s0 + oQl + aQ + offA);
#pragma unroll
            for (int nt2 = 0; nt2 < 4; nt2++) {
                uint32_t bh4[4], bl4[4];
                LDSM_X4(bh4, sKh + nt2 * 2048 + offB);
                LDSM_X4(bl4, sKh + FTILE + nt2 * 2048 + offB);
                MMA16816(sc[2 * nt2],     ah, bh4[0], bh4[1]);
                MMA16816(sc[2 * nt2 + 1], ah, bh4[2], bh4[3]);
                MMA16816(sc[2 * nt2],     ah, bl4[0], bl4[1]);
                MMA16816(sc[2 * nt2 + 1], ah, bl4[2], bl4[3]);
                MMA16816(sc[2 * nt2],     al, bh4[0], bh4[1]);
                MMA16816(sc[2 * nt2 + 1], al, bh4[2], bh4[3]);
            }
        }

        if (kt >= 2 * qt) {
            const int baser = qt * 128 + wm + (lane >> 2);
            const int baseg = kt * 64 + ((lane & 3) << 1);
#pragma unroll
            for (int nt = 0; nt < 8; nt++)
#pragma unroll
                for (int j = 0; j < 4; j++) {
                    const int row = baser + ((j >> 1) << 3);
                    const int g   = baseg + nt * 8 + (j & 1);
                    if (g > row) sc[nt][j] = -1e30f;
                }
        }

#pragma unroll
        for (int hh = 0; hh < 2; hh++) {
            float rm = -1e30f;
#pragma unroll
            for (int nt = 0; nt < 8; nt++)
                rm = fmaxf(rm, fmaxf(sc[nt][2 * hh], sc[nt][2 * hh + 1]));
            rm = fmaxf(rm, __shfl_xor_sync(0xffffffffu, rm, 1));
            rm = fmaxf(rm, __shfl_xor_sync(0xffffffffu, rm, 2));
            const float mnew = fmaxf(mrow[hh], rm);
            const float corr = fast_exp2(mrow[hh] - mnew);
            mrow[hh] = mnew;
            float rs = 0.0f;
#pragma unroll
            for (int nt = 0; nt < 8; nt++) {
                sc[nt][2 * hh]     = fast_exp2(sc[nt][2 * hh] - mnew);
                sc[nt][2 * hh + 1] = fast_exp2(sc[nt][2 * hh + 1] - mnew);
                rs += sc[nt][2 * hh] + sc[nt][2 * hh + 1];
            }
            rs += __shfl_xor_sync(0xffffffffu, rs, 1);
            rs += __shfl_xor_sync(0xffffffffu, rs, 2);
            lrow[hh] = lrow[hh] * corr + rs;
#pragma unroll
            for (int nt = 0; nt < 8; nt++) {
                o[nt][2 * hh]     *= corr;
                o[nt][2 * hh + 1] *= corr;
            }
        }

#pragma unroll
        for (int t = 0; t < 4; t++) {
            const int vrow = t * 16 + vrowb;
            uint32_t ap[4], alp[4];
            pack_hl(sc[2 * t][0],     sc[2 * t][1],     ap[0], alp[0]);
            pack_hl(sc[2 * t][2],     sc[2 * t][3],     ap[1], alp[1]);
            pack_hl(sc[2 * t + 1][0], sc[2 * t + 1][1], ap[2], alp[2]);
            pack_hl(sc[2 * t + 1][2], sc[2 * t + 1][3], ap[3], alp[3]);
#pragma unroll
            for (int nt2 = 0; nt2 < 4; nt2++) {
                const int col16 = nt2 * 2 + vsel;
                const uint32_t vaddr = (uint32_t)(vrow * 128)
                                     + (uint32_t)((col16 ^ (vrow & 7)) << 4);
                uint32_t bh4[4], bl4[4];
                LDSM_X4_T(bh4, sV + vaddr);
                LDSM_X4_T(bl4, sV + FTILE + vaddr);
                MMA16816(o[2 * nt2],     ap,  bh4[0], bh4[1]);
                MMA16816(o[2 * nt2 + 1], ap,  bh4[2], bh4[3]);
                MMA16816(o[2 * nt2],     ap,  bl4[0], bl4[1]);
                MMA16816(o[2 * nt2 + 1], ap,  bl4[2], bl4[3]);
                MMA16816(o[2 * nt2],     alp, bh4[0], bh4[1]);
                MMA16816(o[2 * nt2 + 1], alp, bh4[2], bh4[3]);
            }
        }
    }

    const float inv0 = 1.0f / lrow[0];
    const float inv1 = 1.0f / lrow[1];
    const int b = bh >> 4, h = bh & 15;
    const int r0 = qt * 128 + wm + (lane >> 2);
    const int c0 = h * 64 + ((lane & 3) << 1);
#pragma unroll
    for (int nt = 0; nt < 8; nt++) {
        uint32_t hi, lo;
        pack_hl(o[nt][0] * inv0, o[nt][1] * inv0, hi, lo);
        const size_t p0 = (size_t)(b * 2048 + r0) * 1024 + c0 + nt * 8;
        *(uint32_t*)&g_ctxh[p0] = hi;
        *(uint32_t*)&g_ctxl[p0] = lo;
        pack_hl(o[nt][2] * inv1, o[nt][3] * inv1, hi, lo);
        const size_t p1 = (size_t)(b * 2048 + r0 + 8) * 1024 + c0 + nt * 8;
        *(uint32_t*)&g_ctxh[p1] = hi;
        *(uint32_t*)&g_ctxl[p1] = lo;
    }
}

// ---------------------------------------------------------------------------
// Launch.  Input order (metadata): x, Wk, Wq, Wv, Wo, bo
// ---------------------------------------------------------------------------
extern "C" void kernel_launch(void* const* d_in, const int* in_sizes, int n_in,
                              void* d_out, int out_size)
{
    const float* x  = (const float*)d_in[0];
    const float* Wk = (const float*)d_in[1];
    const float* Wq = (const float*)d_in[2];
    const float* Wv = (const float*)d_in[3];
    const float* Wo = (const float*)d_in[4];
    const float* bo = (const float*)d_in[5];
    float* out = (float*)d_out;

    static bool attr_done = false;
    if (!attr_done) {
        cudaFuncSetAttribute(gemm_kernel<0>,
                             cudaFuncAttributeMaxDynamicSharedMemorySize, GEMM_DYN_SMEM);
        cudaFuncSetAttribute(gemm_kernel<1>,
                             cudaFuncAttributeMaxDynamicSharedMemorySize, GEMM_DYN_SMEM);
        cudaFuncSetAttribute(flash_mma_kernel,
                             cudaFuncAttributeMaxDynamicSharedMemorySize, FLASH_SMEM);
        // KEY CHANGE: request the maximum L1/smem carveout so TWO 96KB CTAs
        // fit per SM (228KB unified on sm_103a). Without this the driver
        // picks the smallest carveout fitting ONE block -> occ capped at
        // 1 CTA/SM (measured 11.1% on gemm<1> in R8).
        cudaFuncSetAttribute(gemm_kernel<0>,
                             cudaFuncAttributePreferredSharedMemoryCarveout,
                             cudaSharedmemCarveoutMaxShared);
        cudaFuncSetAttribute(gemm_kernel<1>,
                             cudaFuncAttributePreferredSharedMemoryCarveout,
                             cudaSharedmemCarveoutMaxShared);
        cudaFuncSetAttribute(flash_mma_kernel,
                             cudaFuncAttributePreferredSharedMemoryCarveout,
                             cudaSharedmemCarveoutMaxShared);
        attr_done = true;
    }

    split_all_kernel<<<12288, 256>>>((const float4*)x, (const float4*)Wq,
                                     (const float4*)Wk, (const float4*)Wv,
                                     (const float4*)Wo);

    // QKV projection: M=8192, virtual N = [Wq | Wk | Wv] = 3072
    dim3 g1(MTOT / 128, 3072 / 128);     // 64 x 24, 128-thread CTAs
    gemm_kernel<0><<<g1, 128, GEMM_DYN_SMEM>>>(nullptr, nullptr);

    dim3 g2(S_ / 128, B_ * H_);          // 16 x 64
    flash_mma_kernel<<<g2, 256, FLASH_SMEM>>>();

    // Output projection: M=8192, N=1024 (+ bias)
    dim3 g3(MTOT / 128, 1024 / 128);     // 64 x 8
    gemm_kernel<1><<<g3, 128, GEMM_DYN_SMEM>>>(bo, out);
}